// round 1
// baseline (speedup 1.0000x reference)
#include <cuda_runtime.h>
#include <math.h>

#define SS  2048
#define BB  16
#define DD  1024
#define HH  8
#define DHH 128
#define MM  (SS*BB)        // 32768 token rows
#define BDD (BB*DD)        // 16384, stride between consecutive s for fixed b

// Scratch (device globals: allocation-free per harness rules)
__device__ float g_h  [(size_t)MM*DD];
__device__ float g_pq [(size_t)MM*DD];
__device__ float g_pk [(size_t)MM*DD];
__device__ float g_v  [(size_t)MM*DD];
__device__ float g_att[(size_t)MM*DD];
__device__ float g_kv [BB*HH*DHH*DHH];
__device__ float g_z  [BB*HH*DHH];

// ---------------------------------------------------------------------------
// h = x + sinusoidal positional encoding (broadcast over B)
// ---------------------------------------------------------------------------
__global__ void pe_add(const float* __restrict__ x, float* __restrict__ h) {
    size_t i4 = (size_t)blockIdx.x * blockDim.x + threadIdx.x;
    size_t e  = i4 * 4;
    int d = (int)(e % DD);          // even (e%4==0, DD%4==0)
    int m = (int)(e / DD);
    int s = m / BB;
    const float cc = -9.210340371976184f / (float)DD;   // -ln(10000)/D
    float a0 = (float)s * expf((float)d * cc);
    float a1 = (float)s * expf((float)(d + 2) * cc);
    float4 xv = reinterpret_cast<const float4*>(x)[i4];
    float4 o;
    o.x = xv.x + sinf(a0);
    o.y = xv.y + cosf(a0);
    o.z = xv.z + sinf(a1);
    o.w = xv.w + cosf(a1);
    reinterpret_cast<float4*>(h)[i4] = o;
}

// ---------------------------------------------------------------------------
// C[m,n] = act( sum_k A[m,k]*W[n,k] + bias[n] )
// A: [MM, DD] row-major, W: [DD, DD] row-major (torch Linear weight)
// 128x128 tile, Kt=8, 256 threads, 8x8 per thread, double-buffered smem.
// ACT=1 -> phi(u)=elu(u)+1 = (u>0 ? u+1 : exp(u))
// ---------------------------------------------------------------------------
template<int ACT>
__global__ void __launch_bounds__(256) gemm_nt(const float* __restrict__ A,
                                               const float* __restrict__ W,
                                               const float* __restrict__ bias,
                                               float* __restrict__ C) {
    __shared__ float As[2][8][132];
    __shared__ float Bs[2][8][132];
    const int tid  = threadIdx.x;
    const int tx   = tid & 15, ty = tid >> 4;
    const int row0 = blockIdx.y * 128;
    const int col0 = blockIdx.x * 128;
    const int lr   = tid >> 1;          // 0..127 tile row to load
    const int lc   = (tid & 1) << 2;    // 0 or 4 (k offset within chunk)
    const float* Ap = A + (size_t)(row0 + lr) * DD + lc;
    const float* Wp = W + (size_t)(col0 + lr) * DD + lc;

    float acc[8][8];
#pragma unroll
    for (int i = 0; i < 8; i++)
#pragma unroll
        for (int j = 0; j < 8; j++) acc[i][j] = 0.f;

    float4 av = *reinterpret_cast<const float4*>(Ap);
    float4 wv = *reinterpret_cast<const float4*>(Wp);
    As[0][lc+0][lr]=av.x; As[0][lc+1][lr]=av.y; As[0][lc+2][lr]=av.z; As[0][lc+3][lr]=av.w;
    Bs[0][lc+0][lr]=wv.x; Bs[0][lc+1][lr]=wv.y; Bs[0][lc+2][lr]=wv.z; Bs[0][lc+3][lr]=wv.w;
    __syncthreads();

    int buf = 0;
    for (int kt = 0; kt < DD/8; kt++) {
        float4 av2, wv2;
        if (kt < DD/8 - 1) {
            av2 = *reinterpret_cast<const float4*>(Ap + (kt+1)*8);
            wv2 = *reinterpret_cast<const float4*>(Wp + (kt+1)*8);
        }
#pragma unroll
        for (int kk = 0; kk < 8; kk++) {
            float a[8], b[8];
            *reinterpret_cast<float4*>(a)   = *reinterpret_cast<const float4*>(&As[buf][kk][ty*8]);
            *reinterpret_cast<float4*>(a+4) = *reinterpret_cast<const float4*>(&As[buf][kk][ty*8+4]);
            *reinterpret_cast<float4*>(b)   = *reinterpret_cast<const float4*>(&Bs[buf][kk][tx*8]);
            *reinterpret_cast<float4*>(b+4) = *reinterpret_cast<const float4*>(&Bs[buf][kk][tx*8+4]);
#pragma unroll
            for (int i = 0; i < 8; i++)
#pragma unroll
                for (int j = 0; j < 8; j++)
                    acc[i][j] += a[i] * b[j];
        }
        if (kt < DD/8 - 1) {
            buf ^= 1;
            As[buf][lc+0][lr]=av2.x; As[buf][lc+1][lr]=av2.y; As[buf][lc+2][lr]=av2.z; As[buf][lc+3][lr]=av2.w;
            Bs[buf][lc+0][lr]=wv2.x; Bs[buf][lc+1][lr]=wv2.y; Bs[buf][lc+2][lr]=wv2.z; Bs[buf][lc+3][lr]=wv2.w;
            __syncthreads();
        }
    }

#pragma unroll
    for (int i = 0; i < 8; i++) {
        float out[8];
#pragma unroll
        for (int j = 0; j < 8; j++) {
            float u = acc[i][j] + bias[col0 + tx*8 + j];
            if (ACT) u = (u > 0.f) ? (u + 1.f) : expf(u);
            out[j] = u;
        }
        float* cp = C + (size_t)(row0 + ty*8 + i) * DD + col0 + tx*8;
        *reinterpret_cast<float4*>(cp)     = *reinterpret_cast<const float4*>(out);
        *reinterpret_cast<float4*>(cp + 4) = *reinterpret_cast<const float4*>(out + 4);
    }
}

// ---------------------------------------------------------------------------
// Per (b,h): kv[d,e] = sum_s pk[s,d]*v[s,e]   (128x128, K=S=2048)
//            z[d]    = sum_s pk[s,d]
// One block per (b,h) pair; 256 threads, 8x8 micro-tile, double-buffered.
// ---------------------------------------------------------------------------
__global__ void __launch_bounds__(256) kvz_kernel(const float* __restrict__ pk,
                                                  const float* __restrict__ v,
                                                  float* __restrict__ kv,
                                                  float* __restrict__ z) {
    __shared__ float Ps[2][8][128];
    __shared__ float Vs[2][8][128];
    const int pair = blockIdx.x;
    const size_t base = (size_t)(pair / HH) * DD + (size_t)(pair % HH) * DHH;
    const int tid = threadIdx.x;
    const int tx  = tid & 15, ty = tid >> 4;
    const int si  = tid >> 5;           // 0..7 (s within chunk)
    const int c4  = (tid & 31) << 2;    // 0..124
    const float* Pp = pk + (size_t)si * BDD + base + c4;
    const float* Vp = v  + (size_t)si * BDD + base + c4;

    float acc[8][8]; float zacc[8];
#pragma unroll
    for (int i = 0; i < 8; i++) {
        zacc[i] = 0.f;
#pragma unroll
        for (int j = 0; j < 8; j++) acc[i][j] = 0.f;
    }

    float4 pv = *reinterpret_cast<const float4*>(Pp);
    float4 vv = *reinterpret_cast<const float4*>(Vp);
    *reinterpret_cast<float4*>(&Ps[0][si][c4]) = pv;
    *reinterpret_cast<float4*>(&Vs[0][si][c4]) = vv;
    __syncthreads();

    int buf = 0;
    for (int sc = 0; sc < SS/8; sc++) {
        float4 pv2, vv2;
        if (sc < SS/8 - 1) {
            pv2 = *reinterpret_cast<const float4*>(Pp + (size_t)(sc+1)*8*BDD);
            vv2 = *reinterpret_cast<const float4*>(Vp + (size_t)(sc+1)*8*BDD);
        }
#pragma unroll
        for (int kk = 0; kk < 8; kk++) {
            float a[8], b[8];
            *reinterpret_cast<float4*>(a)   = *reinterpret_cast<const float4*>(&Ps[buf][kk][ty*8]);
            *reinterpret_cast<float4*>(a+4) = *reinterpret_cast<const float4*>(&Ps[buf][kk][ty*8+4]);
            *reinterpret_cast<float4*>(b)   = *reinterpret_cast<const float4*>(&Vs[buf][kk][tx*8]);
            *reinterpret_cast<float4*>(b+4) = *reinterpret_cast<const float4*>(&Vs[buf][kk][tx*8+4]);
#pragma unroll
            for (int i = 0; i < 8; i++) {
                zacc[i] += a[i];
#pragma unroll
                for (int j = 0; j < 8; j++)
                    acc[i][j] += a[i] * b[j];
            }
        }
        if (sc < SS/8 - 1) {
            buf ^= 1;
            *reinterpret_cast<float4*>(&Ps[buf][si][c4]) = pv2;
            *reinterpret_cast<float4*>(&Vs[buf][si][c4]) = vv2;
            __syncthreads();
        }
    }

#pragma unroll
    for (int i = 0; i < 8; i++) {
        float* op = kv + (size_t)pair * DHH * DHH + (size_t)(ty*8 + i) * DHH + tx*8;
        *reinterpret_cast<float4*>(op)     = *reinterpret_cast<const float4*>(&acc[i][0]);
        *reinterpret_cast<float4*>(op + 4) = *reinterpret_cast<const float4*>(&acc[i][4]);
    }
    if (tx == 0) {
#pragma unroll
        for (int i = 0; i < 8; i++)
            z[pair*DHH + ty*8 + i] = zacc[i];
    }
}

// ---------------------------------------------------------------------------
// Per (b,h), per 128-row s-tile:
//   num[s,e] = sum_d pq[s,d]*kv[d,e];  den[s] = sum_d pq[s,d]*z[d]
//   att[s,e] = num / (den + 1e-6)
// ---------------------------------------------------------------------------
__global__ void __launch_bounds__(256) attn_kernel(const float* __restrict__ pq,
                                                   const float* __restrict__ kv,
                                                   const float* __restrict__ z,
                                                   float* __restrict__ att) {
    __shared__ float Qs[2][8][132];
    __shared__ float Ks[2][8][128];
    __shared__ float zs[2][8];
    const int s0   = blockIdx.x * 128;
    const int pair = blockIdx.y;
    const size_t base = (size_t)(pair / HH) * DD + (size_t)(pair % HH) * DHH;
    const int tid = threadIdx.x;
    const int tx  = tid & 15, ty = tid >> 4;
    const int lr  = tid >> 1;
    const int lc  = (tid & 1) << 2;
    const float* Qp = pq + (size_t)(s0 + lr) * BDD + base + lc;
    const float* Kp = kv + (size_t)pair * DHH * DHH;
    const int di = tid >> 5, e4 = (tid & 31) << 2;

    float acc[8][8]; float dacc[8];
#pragma unroll
    for (int i = 0; i < 8; i++) {
        dacc[i] = 0.f;
#pragma unroll
        for (int j = 0; j < 8; j++) acc[i][j] = 0.f;
    }

    float4 qv = *reinterpret_cast<const float4*>(Qp);
    Qs[0][lc+0][lr]=qv.x; Qs[0][lc+1][lr]=qv.y; Qs[0][lc+2][lr]=qv.z; Qs[0][lc+3][lr]=qv.w;
    *reinterpret_cast<float4*>(&Ks[0][di][e4]) =
        *reinterpret_cast<const float4*>(Kp + (size_t)di * DHH + e4);
    if (tid < 8) zs[0][tid] = z[pair*DHH + tid];
    __syncthreads();

    int buf = 0;
    for (int kc = 0; kc < DHH/8; kc++) {
        float4 qv2, kv2; float zreg = 0.f;
        if (kc < DHH/8 - 1) {
            qv2 = *reinterpret_cast<const float4*>(Qp + (kc+1)*8);
            kv2 = *reinterpret_cast<const float4*>(Kp + (size_t)((kc+1)*8 + di) * DHH + e4);
            if (tid < 8) zreg = z[pair*DHH + (kc+1)*8 + tid];
        }
#pragma unroll
        for (int kk = 0; kk < 8; kk++) {
            float a[8], b[8];
            *reinterpret_cast<float4*>(a)   = *reinterpret_cast<const float4*>(&Qs[buf][kk][ty*8]);
            *reinterpret_cast<float4*>(a+4) = *reinterpret_cast<const float4*>(&Qs[buf][kk][ty*8+4]);
            *reinterpret_cast<float4*>(b)   = *reinterpret_cast<const float4*>(&Ks[buf][kk][tx*8]);
            *reinterpret_cast<float4*>(b+4) = *reinterpret_cast<const float4*>(&Ks[buf][kk][tx*8+4]);
            float zv = zs[buf][kk];
#pragma unroll
            for (int i = 0; i < 8; i++) {
                dacc[i] += a[i] * zv;
#pragma unroll
                for (int j = 0; j < 8; j++)
                    acc[i][j] += a[i] * b[j];
            }
        }
        if (kc < DHH/8 - 1) {
            buf ^= 1;
            Qs[buf][lc+0][lr]=qv2.x; Qs[buf][lc+1][lr]=qv2.y; Qs[buf][lc+2][lr]=qv2.z; Qs[buf][lc+3][lr]=qv2.w;
            *reinterpret_cast<float4*>(&Ks[buf][di][e4]) = kv2;
            if (tid < 8) zs[buf][tid] = zreg;
            __syncthreads();
        }
    }

#pragma unroll
    for (int i = 0; i < 8; i++) {
        float inv = 1.f / (dacc[i] + 1e-6f);
        float out[8];
#pragma unroll
        for (int j = 0; j < 8; j++) out[j] = acc[i][j] * inv;
        float* op = att + (size_t)(s0 + ty*8 + i) * BDD + base + tx*8;
        *reinterpret_cast<float4*>(op)     = *reinterpret_cast<const float4*>(out);
        *reinterpret_cast<float4*>(op + 4) = *reinterpret_cast<const float4*>(out + 4);
    }
}

// ---------------------------------------------------------------------------
extern "C" void kernel_launch(void* const* d_in, const int* in_sizes, int n_in,
                              void* d_out, int out_size) {
    const float* x  = (const float*)d_in[0];
    const float* Wq = (const float*)d_in[1];
    const float* bq = (const float*)d_in[2];
    const float* Wk = (const float*)d_in[3];
    const float* bk = (const float*)d_in[4];
    const float* Wv = (const float*)d_in[5];
    const float* bv = (const float*)d_in[6];
    const float* Wo = (const float*)d_in[7];
    const float* bo = (const float*)d_in[8];
    float* out = (float*)d_out;
    (void)in_sizes; (void)n_in; (void)out_size;

    float *h, *pq, *pk, *v, *att, *kv, *z;
    cudaGetSymbolAddress((void**)&h,   g_h);
    cudaGetSymbolAddress((void**)&pq,  g_pq);
    cudaGetSymbolAddress((void**)&pk,  g_pk);
    cudaGetSymbolAddress((void**)&v,   g_v);
    cudaGetSymbolAddress((void**)&att, g_att);
    cudaGetSymbolAddress((void**)&kv,  g_kv);
    cudaGetSymbolAddress((void**)&z,   g_z);

    // h = x + pe
    pe_add<<<(MM*(size_t)DD)/4/256, 256>>>(x, h);

    // projections (elu+1 fused for q,k)
    dim3 gproj(DD/128, MM/128);   // (8, 256)
    gemm_nt<1><<<gproj, 256>>>(h, Wq, bq, pq);
    gemm_nt<1><<<gproj, 256>>>(h, Wk, bk, pk);
    gemm_nt<0><<<gproj, 256>>>(h, Wv, bv, v);

    // kv state + normalizer
    kvz_kernel<<<BB*HH, 256>>>(pk, v, kv, z);

    // num/den + normalize -> att
    attn_kernel<<<dim3(SS/128, BB*HH), 256>>>(pq, kv, z, att);

    // output projection
    gemm_nt<0><<<gproj, 256>>>(att, Wo, bo, out);
}

// round 5
// speedup vs baseline: 2.2096x; 2.2096x over previous
#include <cuda_runtime.h>
#include <cuda_bf16.h>
#include <cstdint>
#include <math.h>

#define SS  2048
#define BB  16
#define DD  1024
#define HH  8
#define DHH 128
#define MM  (SS*BB)        // 32768 token rows
#define BDD (BB*DD)        // 16384

// ---------------- scratch (device globals; allocation-free) ----------------
__device__ __nv_bfloat16 g_h_hi [(size_t)MM*DD];
__device__ __nv_bfloat16 g_h_lo [(size_t)MM*DD];
__device__ __nv_bfloat16 g_a_hi [(size_t)MM*DD];   // att split
__device__ __nv_bfloat16 g_a_lo [(size_t)MM*DD];
__device__ __nv_bfloat16 g_w_hi [4][(size_t)DD*DD];
__device__ __nv_bfloat16 g_w_lo [4][(size_t)DD*DD];
__device__ float g_pq [(size_t)MM*DD];
__device__ float g_pk [(size_t)MM*DD];
__device__ float g_v  [(size_t)MM*DD];
__device__ float g_kv [BB*HH*DHH*DHH];
__device__ float g_z  [BB*HH*DHH];

// ---------------- helpers ----------------
__device__ __forceinline__ uint32_t smem_u32(const void* p) {
    uint32_t a;
    asm("{ .reg .u64 t; cvta.to.shared.u64 t, %1; cvt.u32.u64 %0, t; }" : "=r"(a) : "l"(p));
    return a;
}
__device__ __forceinline__ void ldsm4(uint32_t* r, uint32_t a) {
    asm volatile("ldmatrix.sync.aligned.m8n8.x4.shared.b16 {%0,%1,%2,%3}, [%4];"
        : "=r"(r[0]), "=r"(r[1]), "=r"(r[2]), "=r"(r[3]) : "r"(a));
}
__device__ __forceinline__ void ldsm2(uint32_t* r, uint32_t a) {
    asm volatile("ldmatrix.sync.aligned.m8n8.x2.shared.b16 {%0,%1}, [%2];"
        : "=r"(r[0]), "=r"(r[1]) : "r"(a));
}
__device__ __forceinline__ void mma16816(float* c, const uint32_t* a, const uint32_t* b) {
    asm volatile("mma.sync.aligned.m16n8k16.row.col.f32.bf16.bf16.f32 "
        "{%0,%1,%2,%3}, {%4,%5,%6,%7}, {%8,%9}, {%0,%1,%2,%3};"
        : "+f"(c[0]), "+f"(c[1]), "+f"(c[2]), "+f"(c[3])
        : "r"(a[0]), "r"(a[1]), "r"(a[2]), "r"(a[3]), "r"(b[0]), "r"(b[1]));
}
__device__ __forceinline__ void split1(float x, __nv_bfloat16& h, __nv_bfloat16& l) {
    h = __float2bfloat16(x);
    l = __float2bfloat16(x - __bfloat162float(h));
}

// ---------------------------------------------------------------------------
// h = x + PE, split to bf16 hi/lo
// ---------------------------------------------------------------------------
__global__ void pe_add_split(const float* __restrict__ x,
                             __nv_bfloat16* __restrict__ hh,
                             __nv_bfloat16* __restrict__ hl) {
    size_t i4 = (size_t)blockIdx.x * blockDim.x + threadIdx.x;
    size_t e  = i4 * 4;
    int d = (int)(e % DD);
    int m = (int)(e / DD);
    int s = m / BB;
    const float cc = -9.210340371976184f / (float)DD;
    float a0 = (float)s * expf((float)d * cc);
    float a1 = (float)s * expf((float)(d + 2) * cc);
    float4 xv = reinterpret_cast<const float4*>(x)[i4];
    float o0 = xv.x + sinf(a0);
    float o1 = xv.y + cosf(a0);
    float o2 = xv.z + sinf(a1);
    float o3 = xv.w + cosf(a1);
    __nv_bfloat16 h0,h1,h2,h3,l0,l1,l2,l3;
    split1(o0,h0,l0); split1(o1,h1,l1); split1(o2,h2,l2); split1(o3,h3,l3);
    __nv_bfloat162* hp = reinterpret_cast<__nv_bfloat162*>(hh) + i4*2;
    __nv_bfloat162* lp = reinterpret_cast<__nv_bfloat162*>(hl) + i4*2;
    hp[0] = __nv_bfloat162(h0,h1); hp[1] = __nv_bfloat162(h2,h3);
    lp[0] = __nv_bfloat162(l0,l1); lp[1] = __nv_bfloat162(l2,l3);
}

__global__ void split_arr(const float* __restrict__ src,
                          __nv_bfloat16* __restrict__ hi,
                          __nv_bfloat16* __restrict__ lo) {
    size_t i4 = (size_t)blockIdx.x * blockDim.x + threadIdx.x;
    float4 v = reinterpret_cast<const float4*>(src)[i4];
    __nv_bfloat16 h0,h1,h2,h3,l0,l1,l2,l3;
    split1(v.x,h0,l0); split1(v.y,h1,l1); split1(v.z,h2,l2); split1(v.w,h3,l3);
    __nv_bfloat162* hp = reinterpret_cast<__nv_bfloat162*>(hi) + i4*2;
    __nv_bfloat162* lp = reinterpret_cast<__nv_bfloat162*>(lo) + i4*2;
    hp[0] = __nv_bfloat162(h0,h1); hp[1] = __nv_bfloat162(h2,h3);
    lp[0] = __nv_bfloat162(l0,l1); lp[1] = __nv_bfloat162(l2,l3);
}

// ---------------------------------------------------------------------------
// bf16x3 GEMM via mma.sync: C[m,n] = act( sum_k A[m,k]*W[n,k] + bias[n] )
// CTA 128x128, 256 thr (2x4 warps, warp tile 64x32), K-chunk 32, dbl-buffered.
// smem tile: 128 rows x 32 bf16, padded row stride 40 bf16 (80 B).
// ---------------------------------------------------------------------------
#define KC2   32
#define NKC   (DD/KC2)        // 32
#define TPADB 80              // bytes per padded row
#define TBYTES (128*TPADB)    // 10240
#define STAGEB (4*TBYTES)     // 40960
#define GSMEM  (2*STAGEB)     // 81920

template<int ACT>
__global__ void __launch_bounds__(256, 1) gemm_mma(
    const __nv_bfloat16* __restrict__ Ahg, const __nv_bfloat16* __restrict__ Alg,
    const __nv_bfloat16* __restrict__ Bhg, const __nv_bfloat16* __restrict__ Blg,
    const float* __restrict__ bias, float* __restrict__ C) {
    extern __shared__ char sm[];
    const int tid = threadIdx.x;
    const int l   = tid & 31;
    const int wid = tid >> 5;
    const int wm  = wid >> 2;       // 0..1
    const int wn  = wid & 3;        // 0..3
    const int m0  = blockIdx.y * 128;
    const int n0  = blockIdx.x * 128;

    const __nv_bfloat16* srcs[4] = {Ahg, Alg, Bhg, Blg};
    const int r0s[4] = {m0, m0, n0, n0};
    const int lrow0 = tid >> 2;      // 0..63
    const int lcol  = tid & 3;       // 0..3 (16B chunk)

    // preload chunk 0 into stage 0
#pragma unroll
    for (int t = 0; t < 4; t++) {
        const float4* gp = reinterpret_cast<const float4*>(srcs[t]);
        char* tp = sm + t*TBYTES;
#pragma unroll
        for (int i = 0; i < 2; i++) {
            int r = lrow0 + i*64;
            float4 v = gp[((size_t)(r0s[t] + r) * DD) / 8 + lcol];
            *reinterpret_cast<float4*>(tp + r*TPADB + lcol*16) = v;
        }
    }
    __syncthreads();

    float acc[4][4][4];
#pragma unroll
    for (int mt = 0; mt < 4; mt++)
#pragma unroll
        for (int nt = 0; nt < 4; nt++)
#pragma unroll
            for (int i = 0; i < 4; i++) acc[mt][nt][i] = 0.f;

    const uint32_t sbase = smem_u32(sm);
    const uint32_t aoff0 = (uint32_t)((wm*64 + (l & 15)) * TPADB + ((l >> 4) << 4));
    const uint32_t boff0 = (uint32_t)((wn*32 + (l & 7)) * TPADB + (((l >> 3) & 1) << 4));

    for (int c = 0; c < NKC; c++) {
        const uint32_t cb = sbase + (c & 1)*STAGEB;
        float4 pre[8];
        if (c < NKC - 1) {
            const int kc = (c + 1) * KC2;
#pragma unroll
            for (int t = 0; t < 4; t++) {
                const float4* gp = reinterpret_cast<const float4*>(srcs[t]);
#pragma unroll
                for (int i = 0; i < 2; i++) {
                    int r = lrow0 + i*64;
                    pre[t*2+i] = gp[((size_t)(r0s[t] + r) * DD + kc) / 8 + lcol];
                }
            }
        }

#pragma unroll
        for (int ks = 0; ks < 2; ks++) {
            const uint32_t ah_b = cb + aoff0 + ks*32;
            const uint32_t al_b = ah_b + TBYTES;
            const uint32_t bh_b = cb + 2*TBYTES + boff0 + ks*32;
            const uint32_t bl_b = bh_b + TBYTES;

            uint32_t ah[4][4], bh[4][2], bx[4][2];
#pragma unroll
            for (int mt = 0; mt < 4; mt++) ldsm4(ah[mt], ah_b + mt*16*TPADB);
#pragma unroll
            for (int nt = 0; nt < 4; nt++) ldsm2(bh[nt], bh_b + nt*8*TPADB);
#pragma unroll
            for (int mt = 0; mt < 4; mt++)
#pragma unroll
                for (int nt = 0; nt < 4; nt++)
                    mma16816(acc[mt][nt], ah[mt], bh[nt]);
#pragma unroll
            for (int nt = 0; nt < 4; nt++) ldsm2(bx[nt], bl_b + nt*8*TPADB);
#pragma unroll
            for (int mt = 0; mt < 4; mt++)
#pragma unroll
                for (int nt = 0; nt < 4; nt++)
                    mma16816(acc[mt][nt], ah[mt], bx[nt]);
#pragma unroll
            for (int mt = 0; mt < 4; mt++) ldsm4(ah[mt], al_b + mt*16*TPADB);
#pragma unroll
            for (int mt = 0; mt < 4; mt++)
#pragma unroll
                for (int nt = 0; nt < 4; nt++)
                    mma16816(acc[mt][nt], ah[mt], bh[nt]);
        }

        if (c < NKC - 1) {
            char* nb = sm + ((c + 1) & 1)*STAGEB;
#pragma unroll
            for (int t = 0; t < 4; t++) {
#pragma unroll
                for (int i = 0; i < 2; i++) {
                    int r = lrow0 + i*64;
                    *reinterpret_cast<float4*>(nb + t*TBYTES + r*TPADB + lcol*16) = pre[t*2+i];
                }
            }
        }
        __syncthreads();
    }

    // epilogue
    const int gi = l >> 2, ti = l & 3;
#pragma unroll
    for (int mt = 0; mt < 4; mt++) {
        const int ra = m0 + wm*64 + mt*16 + gi;
        const int rb = ra + 8;
#pragma unroll
        for (int nt = 0; nt < 4; nt++) {
            const int col = n0 + wn*32 + nt*8 + ti*2;
            const float b0 = bias[col], b1 = bias[col + 1];
            float u0 = acc[mt][nt][0] + b0;
            float u1 = acc[mt][nt][1] + b1;
            float u2 = acc[mt][nt][2] + b0;
            float u3 = acc[mt][nt][3] + b1;
            if (ACT) {
                u0 = (u0 > 0.f) ? (u0 + 1.f) : expf(u0);
                u1 = (u1 > 0.f) ? (u1 + 1.f) : expf(u1);
                u2 = (u2 > 0.f) ? (u2 + 1.f) : expf(u2);
                u3 = (u3 > 0.f) ? (u3 + 1.f) : expf(u3);
            }
            float2 o01; o01.x = u0; o01.y = u1;
            float2 o23; o23.x = u2; o23.y = u3;
            *reinterpret_cast<float2*>(C + (size_t)ra*DD + col) = o01;
            *reinterpret_cast<float2*>(C + (size_t)rb*DD + col) = o23;
        }
    }
}

// ---------------------------------------------------------------------------
// Per (b,h): kv[d,e] = sum_s pk[s,d]*v[s,e];  z[d] = sum_s pk[s,d]   (fp32)
// ---------------------------------------------------------------------------
__global__ void __launch_bounds__(256) kvz_kernel(const float* __restrict__ pk,
                                                  const float* __restrict__ v,
                                                  float* __restrict__ kv,
                                                  float* __restrict__ z) {
    __shared__ float Ps[2][8][128];
    __shared__ float Vs[2][8][128];
    const int pair = blockIdx.x;
    const size_t base = (size_t)(pair / HH) * DD + (size_t)(pair % HH) * DHH;
    const int tid = threadIdx.x;
    const int tx  = tid & 15, ty = tid >> 4;
    const int si  = tid >> 5;
    const int c4  = (tid & 31) << 2;
    const float* Pp = pk + (size_t)si * BDD + base + c4;
    const float* Vp = v  + (size_t)si * BDD + base + c4;

    float acc[8][8]; float zacc[8];
#pragma unroll
    for (int i = 0; i < 8; i++) {
        zacc[i] = 0.f;
#pragma unroll
        for (int j = 0; j < 8; j++) acc[i][j] = 0.f;
    }

    float4 pv = *reinterpret_cast<const float4*>(Pp);
    float4 vv = *reinterpret_cast<const float4*>(Vp);
    *reinterpret_cast<float4*>(&Ps[0][si][c4]) = pv;
    *reinterpret_cast<float4*>(&Vs[0][si][c4]) = vv;
    __syncthreads();

    int buf = 0;
    for (int sc = 0; sc < SS/8; sc++) {
        float4 pv2, vv2;
        if (sc < SS/8 - 1) {
            pv2 = *reinterpret_cast<const float4*>(Pp + (size_t)(sc+1)*8*BDD);
            vv2 = *reinterpret_cast<const float4*>(Vp + (size_t)(sc+1)*8*BDD);
        }
#pragma unroll
        for (int kk = 0; kk < 8; kk++) {
            float a[8], b[8];
            *reinterpret_cast<float4*>(a)   = *reinterpret_cast<const float4*>(&Ps[buf][kk][ty*8]);
            *reinterpret_cast<float4*>(a+4) = *reinterpret_cast<const float4*>(&Ps[buf][kk][ty*8+4]);
            *reinterpret_cast<float4*>(b)   = *reinterpret_cast<const float4*>(&Vs[buf][kk][tx*8]);
            *reinterpret_cast<float4*>(b+4) = *reinterpret_cast<const float4*>(&Vs[buf][kk][tx*8+4]);
#pragma unroll
            for (int i = 0; i < 8; i++) {
                zacc[i] += a[i];
#pragma unroll
                for (int j = 0; j < 8; j++)
                    acc[i][j] += a[i] * b[j];
            }
        }
        if (sc < SS/8 - 1) {
            buf ^= 1;
            *reinterpret_cast<float4*>(&Ps[buf][si][c4]) = pv2;
            *reinterpret_cast<float4*>(&Vs[buf][si][c4]) = vv2;
            __syncthreads();
        }
    }

#pragma unroll
    for (int i = 0; i < 8; i++) {
        float* op = kv + (size_t)pair * DHH * DHH + (size_t)(ty*8 + i) * DHH + tx*8;
        *reinterpret_cast<float4*>(op)     = *reinterpret_cast<const float4*>(&acc[i][0]);
        *reinterpret_cast<float4*>(op + 4) = *reinterpret_cast<const float4*>(&acc[i][4]);
    }
    if (tx == 0) {
#pragma unroll
        for (int i = 0; i < 8; i++)
            z[pair*DHH + ty*8 + i] = zacc[i];
    }
}

// ---------------------------------------------------------------------------
// attn: num/den + normalize, writes att split to bf16 hi/lo
// ---------------------------------------------------------------------------
__global__ void __launch_bounds__(256) attn_kernel(const float* __restrict__ pq,
                                                   const float* __restrict__ kv,
                                                   const float* __restrict__ z,
                                                   __nv_bfloat16* __restrict__ ah,
                                                   __nv_bfloat16* __restrict__ al) {
    __shared__ float Qs[2][8][132];
    __shared__ float Ks[2][8][128];
    __shared__ float zs[2][8];
    const int s0   = blockIdx.x * 128;
    const int pair = blockIdx.y;
    const size_t base = (size_t)(pair / HH) * DD + (size_t)(pair % HH) * DHH;
    const int tid = threadIdx.x;
    const int tx  = tid & 15, ty = tid >> 4;
    const int lr  = tid >> 1;
    const int lc  = (tid & 1) << 2;
    const float* Qp = pq + (size_t)(s0 + lr) * BDD + base + lc;
    const float* Kp = kv + (size_t)pair * DHH * DHH;
    const int di = tid >> 5, e4 = (tid & 31) << 2;

    float acc[8][8]; float dacc[8];
#pragma unroll
    for (int i = 0; i < 8; i++) {
        dacc[i] = 0.f;
#pragma unroll
        for (int j = 0; j < 8; j++) acc[i][j] = 0.f;
    }

    float4 qv = *reinterpret_cast<const float4*>(Qp);
    Qs[0][lc+0][lr]=qv.x; Qs[0][lc+1][lr]=qv.y; Qs[0][lc+2][lr]=qv.z; Qs[0][lc+3][lr]=qv.w;
    *reinterpret_cast<float4*>(&Ks[0][di][e4]) =
        *reinterpret_cast<const float4*>(Kp + (size_t)di * DHH + e4);
    if (tid < 8) zs[0][tid] = z[pair*DHH + tid];
    __syncthreads();

    int buf = 0;
    for (int kc = 0; kc < DHH/8; kc++) {
        float4 qv2, kv2; float zreg = 0.f;
        if (kc < DHH/8 - 1) {
            qv2 = *reinterpret_cast<const float4*>(Qp + (kc+1)*8);
            kv2 = *reinterpret_cast<const float4*>(Kp + (size_t)((kc+1)*8 + di) * DHH + e4);
            if (tid < 8) zreg = z[pair*DHH + (kc+1)*8 + tid];
        }
#pragma unroll
        for (int kk = 0; kk < 8; kk++) {
            float a[8], b[8];
            *reinterpret_cast<float4*>(a)   = *reinterpret_cast<const float4*>(&Qs[buf][kk][ty*8]);
            *reinterpret_cast<float4*>(a+4) = *reinterpret_cast<const float4*>(&Qs[buf][kk][ty*8+4]);
            *reinterpret_cast<float4*>(b)   = *reinterpret_cast<const float4*>(&Ks[buf][kk][tx*8]);
            *reinterpret_cast<float4*>(b+4) = *reinterpret_cast<const float4*>(&Ks[buf][kk][tx*8+4]);
            float zv = zs[buf][kk];
#pragma unroll
            for (int i = 0; i < 8; i++) {
                dacc[i] += a[i] * zv;
#pragma unroll
                for (int j = 0; j < 8; j++)
                    acc[i][j] += a[i] * b[j];
            }
        }
        if (kc < DHH/8 - 1) {
            buf ^= 1;
            Qs[buf][lc+0][lr]=qv2.x; Qs[buf][lc+1][lr]=qv2.y; Qs[buf][lc+2][lr]=qv2.z; Qs[buf][lc+3][lr]=qv2.w;
            *reinterpret_cast<float4*>(&Ks[buf][di][e4]) = kv2;
            if (tid < 8) zs[buf][tid] = zreg;
            __syncthreads();
        }
    }

#pragma unroll
    for (int i = 0; i < 8; i++) {
        float inv = 1.f / (dacc[i] + 1e-6f);
        __nv_bfloat162 ho[4], lo[4];
#pragma unroll
        for (int j = 0; j < 4; j++) {
            float u0 = acc[i][2*j]   * inv;
            float u1 = acc[i][2*j+1] * inv;
            __nv_bfloat16 h0,h1,l0,l1;
            split1(u0,h0,l0); split1(u1,h1,l1);
            ho[j] = __nv_bfloat162(h0,h1);
            lo[j] = __nv_bfloat162(l0,l1);
        }
        size_t off = (size_t)(s0 + ty*8 + i) * BDD + base + tx*8;
        *reinterpret_cast<uint4*>(ah + off) = *reinterpret_cast<uint4*>(ho);   // FIX: 16B store
        *reinterpret_cast<uint4*>(al + off) = *reinterpret_cast<uint4*>(lo);   // FIX: 16B store
    }
}

// ---------------------------------------------------------------------------
extern "C" void kernel_launch(void* const* d_in, const int* in_sizes, int n_in,
                              void* d_out, int out_size) {
    const float* x  = (const float*)d_in[0];
    const float* Wq = (const float*)d_in[1];
    const float* bq = (const float*)d_in[2];
    const float* Wk = (const float*)d_in[3];
    const float* bk = (const float*)d_in[4];
    const float* Wv = (const float*)d_in[5];
    const float* bv = (const float*)d_in[6];
    const float* Wo = (const float*)d_in[7];
    const float* bo = (const float*)d_in[8];
    float* out = (float*)d_out;
    (void)in_sizes; (void)n_in; (void)out_size;

    __nv_bfloat16 *hh, *hl, *ath, *atl, *wh, *wl;
    float *pq, *pk, *v, *kv, *z;
    cudaGetSymbolAddress((void**)&hh,  g_h_hi);
    cudaGetSymbolAddress((void**)&hl,  g_h_lo);
    cudaGetSymbolAddress((void**)&ath, g_a_hi);
    cudaGetSymbolAddress((void**)&atl, g_a_lo);
    cudaGetSymbolAddress((void**)&wh,  g_w_hi);
    cudaGetSymbolAddress((void**)&wl,  g_w_lo);
    cudaGetSymbolAddress((void**)&pq,  g_pq);
    cudaGetSymbolAddress((void**)&pk,  g_pk);
    cudaGetSymbolAddress((void**)&v,   g_v);
    cudaGetSymbolAddress((void**)&kv,  g_kv);
    cudaGetSymbolAddress((void**)&z,   g_z);

    cudaFuncSetAttribute(gemm_mma<0>, cudaFuncAttributeMaxDynamicSharedMemorySize, GSMEM);
    cudaFuncSetAttribute(gemm_mma<1>, cudaFuncAttributeMaxDynamicSharedMemorySize, GSMEM);

    const size_t WN = (size_t)DD*DD;

    // h = x + pe (split), weight splits
    pe_add_split<<<(MM*(size_t)DD)/4/256, 256>>>(x, hh, hl);
    split_arr<<<WN/4/256, 256>>>(Wq, wh + 0*WN, wl + 0*WN);
    split_arr<<<WN/4/256, 256>>>(Wk, wh + 1*WN, wl + 1*WN);
    split_arr<<<WN/4/256, 256>>>(Wv, wh + 2*WN, wl + 2*WN);
    split_arr<<<WN/4/256, 256>>>(Wo, wh + 3*WN, wl + 3*WN);

    dim3 gproj(DD/128, MM/128);   // (8, 256)
    gemm_mma<1><<<gproj, 256, GSMEM>>>(hh, hl, wh + 0*WN, wl + 0*WN, bq, pq);
    gemm_mma<1><<<gproj, 256, GSMEM>>>(hh, hl, wh + 1*WN, wl + 1*WN, bk, pk);
    gemm_mma<0><<<gproj, 256, GSMEM>>>(hh, hl, wh + 2*WN, wl + 2*WN, bv, v);

    kvz_kernel<<<BB*HH, 256>>>(pk, v, kv, z);
    attn_kernel<<<dim3(SS/128, BB*HH), 256>>>(pq, kv, z, ath, atl);

    gemm_mma<0><<<gproj, 256, GSMEM>>>(ath, atl, wh + 3*WN, wl + 3*WN, bo, out);
}

// round 6
// speedup vs baseline: 2.9735x; 1.3457x over previous
#include <cuda_runtime.h>
#include <cuda_fp16.h>
#include <cstdint>
#include <math.h>

#define SS  2048
#define BB  16
#define DD  1024
#define HH  8
#define DHH 128
#define MM  (SS*BB)        // 32768 token rows
#define BDD (BB*DD)        // 16384
#define WSCALE 64.0f
#define INV_WSCALE (1.0f/64.0f)

// ---------------- scratch (device globals; allocation-free) ----------------
__device__ __half g_h   [(size_t)MM*DD];
__device__ __half g_att [(size_t)MM*DD];
__device__ __half g_w_hi[4][(size_t)DD*DD];
__device__ __half g_w_lo[4][(size_t)DD*DD];
__device__ float g_pq [(size_t)MM*DD];
__device__ float g_pk [(size_t)MM*DD];
__device__ float g_v  [(size_t)MM*DD];
__device__ float g_kvp[4][BB*HH*DHH*DHH];   // split-K partials
__device__ float g_zp [4][BB*HH*DHH];
__device__ float g_kv [BB*HH*DHH*DHH];
__device__ float g_z  [BB*HH*DHH];

// ---------------- helpers ----------------
__device__ __forceinline__ uint32_t smem_u32(const void* p) {
    uint32_t a;
    asm("{ .reg .u64 t; cvta.to.shared.u64 t, %1; cvt.u32.u64 %0, t; }" : "=r"(a) : "l"(p));
    return a;
}
__device__ __forceinline__ void ldsm4(uint32_t* r, uint32_t a) {
    asm volatile("ldmatrix.sync.aligned.m8n8.x4.shared.b16 {%0,%1,%2,%3}, [%4];"
        : "=r"(r[0]), "=r"(r[1]), "=r"(r[2]), "=r"(r[3]) : "r"(a));
}
__device__ __forceinline__ void ldsm2(uint32_t* r, uint32_t a) {
    asm volatile("ldmatrix.sync.aligned.m8n8.x2.shared.b16 {%0,%1}, [%2];"
        : "=r"(r[0]), "=r"(r[1]) : "r"(a));
}
__device__ __forceinline__ void mma16816h(float* c, const uint32_t* a, const uint32_t* b) {
    asm volatile("mma.sync.aligned.m16n8k16.row.col.f32.f16.f16.f32 "
        "{%0,%1,%2,%3}, {%4,%5,%6,%7}, {%8,%9}, {%0,%1,%2,%3};"
        : "+f"(c[0]), "+f"(c[1]), "+f"(c[2]), "+f"(c[3])
        : "r"(a[0]), "r"(a[1]), "r"(a[2]), "r"(a[3]), "r"(b[0]), "r"(b[1]));
}

// ---------------------------------------------------------------------------
// h = x + PE  -> fp16
// ---------------------------------------------------------------------------
__global__ void pe_add_h(const float* __restrict__ x, __half* __restrict__ h) {
    size_t i4 = (size_t)blockIdx.x * blockDim.x + threadIdx.x;
    size_t e  = i4 * 4;
    int d = (int)(e % DD);
    int m = (int)(e / DD);
    int s = m / BB;
    const float cc = -9.210340371976184f / (float)DD;
    float a0 = (float)s * expf((float)d * cc);
    float a1 = (float)s * expf((float)(d + 2) * cc);
    float4 xv = reinterpret_cast<const float4*>(x)[i4];
    __half2* hp = reinterpret_cast<__half2*>(h) + i4*2;
    hp[0] = __floats2half2_rn(xv.x + sinf(a0), xv.y + cosf(a0));
    hp[1] = __floats2half2_rn(xv.z + sinf(a1), xv.w + cosf(a1));
}

// scaled fp16x2 split of weights: s = W*64; hi = fp16(s); lo = fp16(s - hi)
__global__ void split_w(const float* __restrict__ src,
                        __half* __restrict__ hi, __half* __restrict__ lo) {
    size_t i4 = (size_t)blockIdx.x * blockDim.x + threadIdx.x;
    float4 v = reinterpret_cast<const float4*>(src)[i4];
    float s0 = v.x*WSCALE, s1 = v.y*WSCALE, s2 = v.z*WSCALE, s3 = v.w*WSCALE;
    __half h0 = __float2half_rn(s0), h1 = __float2half_rn(s1);
    __half h2 = __float2half_rn(s2), h3 = __float2half_rn(s3);
    __half l0 = __float2half_rn(s0 - __half2float(h0));
    __half l1 = __float2half_rn(s1 - __half2float(h1));
    __half l2 = __float2half_rn(s2 - __half2float(h2));
    __half l3 = __float2half_rn(s3 - __half2float(h3));
    __half2* hp = reinterpret_cast<__half2*>(hi) + i4*2;
    __half2* lp = reinterpret_cast<__half2*>(lo) + i4*2;
    hp[0] = __halves2half2(h0,h1); hp[1] = __halves2half2(h2,h3);
    lp[0] = __halves2half2(l0,l1); lp[1] = __halves2half2(l2,l3);
}

// ---------------------------------------------------------------------------
// 2-pass fp16 GEMM: C[m,n] = act( (sum_k A[m,k]*(Wh+Wl)[n,k])/64 + bias[n] )
// A fp16 single; B split fp16x2 (scaled x64). CTA 128x128, 256 thr, KC=32.
// ---------------------------------------------------------------------------
#define KC2   32
#define NKC   (DD/KC2)        // 32
#define TPADB 80              // bytes per padded row (64B data + 16B pad)
#define TBYTES (128*TPADB)    // 10240
#define STAGEB (3*TBYTES)     // 30720
#define GSMEM  (2*STAGEB)     // 61440

template<int ACT>
__global__ void __launch_bounds__(256, 1) gemm2p(
    const __half* __restrict__ Ag,
    const __half* __restrict__ Bhg, const __half* __restrict__ Blg,
    const float* __restrict__ bias, float* __restrict__ C) {
    extern __shared__ char sm[];
    const int tid = threadIdx.x;
    const int l   = tid & 31;
    const int wid = tid >> 5;
    const int wm  = wid >> 2;       // 0..1
    const int wn  = wid & 3;        // 0..3
    const int m0  = blockIdx.y * 128;
    const int n0  = blockIdx.x * 128;

    const __half* srcs[3] = {Ag, Bhg, Blg};
    const int r0s[3] = {m0, n0, n0};
    const int lrow0 = tid >> 2;      // 0..63
    const int lcol  = tid & 3;       // 0..3 (16B chunk)

    // preload chunk 0 into stage 0
#pragma unroll
    for (int t = 0; t < 3; t++) {
        const float4* gp = reinterpret_cast<const float4*>(srcs[t]);
        char* tp = sm + t*TBYTES;
#pragma unroll
        for (int i = 0; i < 2; i++) {
            int r = lrow0 + i*64;
            float4 v = gp[((size_t)(r0s[t] + r) * DD) / 8 + lcol];
            *reinterpret_cast<float4*>(tp + r*TPADB + lcol*16) = v;
        }
    }
    __syncthreads();

    float acc[4][4][4];
#pragma unroll
    for (int mt = 0; mt < 4; mt++)
#pragma unroll
        for (int nt = 0; nt < 4; nt++)
#pragma unroll
            for (int i = 0; i < 4; i++) acc[mt][nt][i] = 0.f;

    const uint32_t sbase = smem_u32(sm);
    const uint32_t aoff0 = (uint32_t)((wm*64 + (l & 15)) * TPADB + ((l >> 4) << 4));
    const uint32_t boff0 = (uint32_t)((wn*32 + (l & 7)) * TPADB + (((l >> 3) & 1) << 4));

    for (int c = 0; c < NKC; c++) {
        const uint32_t cb = sbase + (c & 1)*STAGEB;
        float4 pre[6];
        if (c < NKC - 1) {
            const int kc = (c + 1) * KC2;
#pragma unroll
            for (int t = 0; t < 3; t++) {
                const float4* gp = reinterpret_cast<const float4*>(srcs[t]);
#pragma unroll
                for (int i = 0; i < 2; i++) {
                    int r = lrow0 + i*64;
                    pre[t*2+i] = gp[((size_t)(r0s[t] + r) * DD + kc) / 8 + lcol];
                }
            }
        }

#pragma unroll
        for (int ks = 0; ks < 2; ks++) {
            const uint32_t a_b  = cb + aoff0 + ks*32;
            const uint32_t bh_b = cb + 1*TBYTES + boff0 + ks*32;
            const uint32_t bl_b = cb + 2*TBYTES + boff0 + ks*32;

            uint32_t ah[4][4], bh[4][2], bx[4][2];
#pragma unroll
            for (int mt = 0; mt < 4; mt++) ldsm4(ah[mt], a_b + mt*16*TPADB);
#pragma unroll
            for (int nt = 0; nt < 4; nt++) ldsm2(bh[nt], bh_b + nt*8*TPADB);
#pragma unroll
            for (int mt = 0; mt < 4; mt++)
#pragma unroll
                for (int nt = 0; nt < 4; nt++)
                    mma16816h(acc[mt][nt], ah[mt], bh[nt]);
#pragma unroll
            for (int nt = 0; nt < 4; nt++) ldsm2(bx[nt], bl_b + nt*8*TPADB);
#pragma unroll
            for (int mt = 0; mt < 4; mt++)
#pragma unroll
                for (int nt = 0; nt < 4; nt++)
                    mma16816h(acc[mt][nt], ah[mt], bx[nt]);
        }

        if (c < NKC - 1) {
            char* nb = sm + ((c + 1) & 1)*STAGEB;
#pragma unroll
            for (int t = 0; t < 3; t++) {
#pragma unroll
                for (int i = 0; i < 2; i++) {
                    int r = lrow0 + i*64;
                    *reinterpret_cast<float4*>(nb + t*TBYTES + r*TPADB + lcol*16) = pre[t*2+i];
                }
            }
        }
        __syncthreads();
    }

    // epilogue
    const int gi = l >> 2, ti = l & 3;
#pragma unroll
    for (int mt = 0; mt < 4; mt++) {
        const int ra = m0 + wm*64 + mt*16 + gi;
        const int rb = ra + 8;
#pragma unroll
        for (int nt = 0; nt < 4; nt++) {
            const int col = n0 + wn*32 + nt*8 + ti*2;
            const float b0 = bias[col], b1 = bias[col + 1];
            float u0 = acc[mt][nt][0]*INV_WSCALE + b0;
            float u1 = acc[mt][nt][1]*INV_WSCALE + b1;
            float u2 = acc[mt][nt][2]*INV_WSCALE + b0;
            float u3 = acc[mt][nt][3]*INV_WSCALE + b1;
            if (ACT) {
                u0 = (u0 > 0.f) ? (u0 + 1.f) : expf(u0);
                u1 = (u1 > 0.f) ? (u1 + 1.f) : expf(u1);
                u2 = (u2 > 0.f) ? (u2 + 1.f) : expf(u2);
                u3 = (u3 > 0.f) ? (u3 + 1.f) : expf(u3);
            }
            float2 o01; o01.x = u0; o01.y = u1;
            float2 o23; o23.x = u2; o23.y = u3;
            *reinterpret_cast<float2*>(C + (size_t)ra*DD + col) = o01;
            *reinterpret_cast<float2*>(C + (size_t)rb*DD + col) = o23;
        }
    }
}

// ---------------------------------------------------------------------------
// kvz split-K: per (pair, chunk): partial kv/z over 512 s values (fp32)
// ---------------------------------------------------------------------------
__global__ void __launch_bounds__(256) kvz_part(const float* __restrict__ pk,
                                                const float* __restrict__ v,
                                                float* __restrict__ kvp,
                                                float* __restrict__ zp) {
    __shared__ float Ps[2][8][128];
    __shared__ float Vs[2][8][128];
    const int pair  = blockIdx.x;
    const int chunk = blockIdx.y;
    const size_t base = (size_t)(pair / HH) * DD + (size_t)(pair % HH) * DHH
                      + (size_t)chunk * 512 * BDD;
    const int tid = threadIdx.x;
    const int tx  = tid & 15, ty = tid >> 4;
    const int si  = tid >> 5;
    const int c4  = (tid & 31) << 2;
    const float* Pp = pk + (size_t)si * BDD + base + c4;
    const float* Vp = v  + (size_t)si * BDD + base + c4;

    float acc[8][8]; float zacc[8];
#pragma unroll
    for (int i = 0; i < 8; i++) {
        zacc[i] = 0.f;
#pragma unroll
        for (int j = 0; j < 8; j++) acc[i][j] = 0.f;
    }

    *reinterpret_cast<float4*>(&Ps[0][si][c4]) = *reinterpret_cast<const float4*>(Pp);
    *reinterpret_cast<float4*>(&Vs[0][si][c4]) = *reinterpret_cast<const float4*>(Vp);
    __syncthreads();

    int buf = 0;
    for (int sc = 0; sc < 512/8; sc++) {
        float4 pv2, vv2;
        if (sc < 512/8 - 1) {
            pv2 = *reinterpret_cast<const float4*>(Pp + (size_t)(sc+1)*8*BDD);
            vv2 = *reinterpret_cast<const float4*>(Vp + (size_t)(sc+1)*8*BDD);
        }
#pragma unroll
        for (int kk = 0; kk < 8; kk++) {
            float a[8], b[8];
            *reinterpret_cast<float4*>(a)   = *reinterpret_cast<const float4*>(&Ps[buf][kk][ty*8]);
            *reinterpret_cast<float4*>(a+4) = *reinterpret_cast<const float4*>(&Ps[buf][kk][ty*8+4]);
            *reinterpret_cast<float4*>(b)   = *reinterpret_cast<const float4*>(&Vs[buf][kk][tx*8]);
            *reinterpret_cast<float4*>(b+4) = *reinterpret_cast<const float4*>(&Vs[buf][kk][tx*8+4]);
#pragma unroll
            for (int i = 0; i < 8; i++) {
                zacc[i] += a[i];
#pragma unroll
                for (int j = 0; j < 8; j++)
                    acc[i][j] += a[i] * b[j];
            }
        }
        if (sc < 512/8 - 1) {
            buf ^= 1;
            *reinterpret_cast<float4*>(&Ps[buf][si][c4]) = pv2;
            *reinterpret_cast<float4*>(&Vs[buf][si][c4]) = vv2;
            __syncthreads();
        }
    }

    float* kvb = kvp + (size_t)chunk * (BB*HH*DHH*DHH) + (size_t)pair * DHH * DHH;
#pragma unroll
    for (int i = 0; i < 8; i++) {
        float* op = kvb + (size_t)(ty*8 + i) * DHH + tx*8;
        *reinterpret_cast<float4*>(op)     = *reinterpret_cast<const float4*>(&acc[i][0]);
        *reinterpret_cast<float4*>(op + 4) = *reinterpret_cast<const float4*>(&acc[i][4]);
    }
    if (tx == 0) {
#pragma unroll
        for (int i = 0; i < 8; i++)
            zp[(size_t)chunk * (BB*HH*DHH) + pair*DHH + ty*8 + i] = zacc[i];
    }
}

__global__ void kvz_reduce(const float* __restrict__ kvp, const float* __restrict__ zp,
                           float* __restrict__ kv, float* __restrict__ z) {
    const size_t KVN = (size_t)BB*HH*DHH*DHH;
    size_t i4 = (size_t)blockIdx.x * blockDim.x + threadIdx.x;
    if (i4 < KVN/4) {
        float4 s = reinterpret_cast<const float4*>(kvp)[i4];
#pragma unroll
        for (int c = 1; c < 4; c++) {
            float4 t = reinterpret_cast<const float4*>(kvp + c*KVN)[i4];
            s.x += t.x; s.y += t.y; s.z += t.z; s.w += t.w;
        }
        reinterpret_cast<float4*>(kv)[i4] = s;
    }
    const size_t ZN = BB*HH*DHH;
    if (i4 < ZN) {
        float s = zp[i4] + zp[ZN + i4] + zp[2*ZN + i4] + zp[3*ZN + i4];
        z[i4] = s;
    }
}

// ---------------------------------------------------------------------------
// attn: num/den + normalize (fp32), writes att as fp16
// ---------------------------------------------------------------------------
__global__ void __launch_bounds__(256) attn_kernel(const float* __restrict__ pq,
                                                   const float* __restrict__ kv,
                                                   const float* __restrict__ z,
                                                   __half* __restrict__ att) {
    __shared__ float Qs[2][8][132];
    __shared__ float Ks[2][8][128];
    __shared__ float zs[2][8];
    const int s0   = blockIdx.x * 128;
    const int pair = blockIdx.y;
    const size_t base = (size_t)(pair / HH) * DD + (size_t)(pair % HH) * DHH;
    const int tid = threadIdx.x;
    const int tx  = tid & 15, ty = tid >> 4;
    const int lr  = tid >> 1;
    const int lc  = (tid & 1) << 2;
    const float* Qp = pq + (size_t)(s0 + lr) * BDD + base + lc;
    const float* Kp = kv + (size_t)pair * DHH * DHH;
    const int di = tid >> 5, e4 = (tid & 31) << 2;

    float acc[8][8]; float dacc[8];
#pragma unroll
    for (int i = 0; i < 8; i++) {
        dacc[i] = 0.f;
#pragma unroll
        for (int j = 0; j < 8; j++) acc[i][j] = 0.f;
    }

    float4 qv = *reinterpret_cast<const float4*>(Qp);
    Qs[0][lc+0][lr]=qv.x; Qs[0][lc+1][lr]=qv.y; Qs[0][lc+2][lr]=qv.z; Qs[0][lc+3][lr]=qv.w;
    *reinterpret_cast<float4*>(&Ks[0][di][e4]) =
        *reinterpret_cast<const float4*>(Kp + (size_t)di * DHH + e4);
    if (tid < 8) zs[0][tid] = z[pair*DHH + tid];
    __syncthreads();

    int buf = 0;
    for (int kc = 0; kc < DHH/8; kc++) {
        float4 qv2, kv2; float zreg = 0.f;
        if (kc < DHH/8 - 1) {
            qv2 = *reinterpret_cast<const float4*>(Qp + (kc+1)*8);
            kv2 = *reinterpret_cast<const float4*>(Kp + (size_t)((kc+1)*8 + di) * DHH + e4);
            if (tid < 8) zreg = z[pair*DHH + (kc+1)*8 + tid];
        }
#pragma unroll
        for (int kk = 0; kk < 8; kk++) {
            float a[8], b[8];
            *reinterpret_cast<float4*>(a)   = *reinterpret_cast<const float4*>(&Qs[buf][kk][ty*8]);
            *reinterpret_cast<float4*>(a+4) = *reinterpret_cast<const float4*>(&Qs[buf][kk][ty*8+4]);
            *reinterpret_cast<float4*>(b)   = *reinterpret_cast<const float4*>(&Ks[buf][kk][tx*8]);
            *reinterpret_cast<float4*>(b+4) = *reinterpret_cast<const float4*>(&Ks[buf][kk][tx*8+4]);
            float zv = zs[buf][kk];
#pragma unroll
            for (int i = 0; i < 8; i++) {
                dacc[i] += a[i] * zv;
#pragma unroll
                for (int j = 0; j < 8; j++)
                    acc[i][j] += a[i] * b[j];
            }
        }
        if (kc < DHH/8 - 1) {
            buf ^= 1;
            Qs[buf][lc+0][lr]=qv2.x; Qs[buf][lc+1][lr]=qv2.y; Qs[buf][lc+2][lr]=qv2.z; Qs[buf][lc+3][lr]=qv2.w;
            *reinterpret_cast<float4*>(&Ks[buf][di][e4]) = kv2;
            if (tid < 8) zs[buf][tid] = zreg;
            __syncthreads();
        }
    }

#pragma unroll
    for (int i = 0; i < 8; i++) {
        float inv = 1.f / (dacc[i] + 1e-6f);
        __half2 ho[4];
#pragma unroll
        for (int j = 0; j < 4; j++)
            ho[j] = __floats2half2_rn(acc[i][2*j] * inv, acc[i][2*j+1] * inv);
        size_t off = (size_t)(s0 + ty*8 + i) * BDD + base + tx*8;
        *reinterpret_cast<uint4*>(att + off) = *reinterpret_cast<uint4*>(ho);
    }
}

// ---------------------------------------------------------------------------
extern "C" void kernel_launch(void* const* d_in, const int* in_sizes, int n_in,
                              void* d_out, int out_size) {
    const float* x  = (const float*)d_in[0];
    const float* Wq = (const float*)d_in[1];
    const float* bq = (const float*)d_in[2];
    const float* Wk = (const float*)d_in[3];
    const float* bk = (const float*)d_in[4];
    const float* Wv = (const float*)d_in[5];
    const float* bv = (const float*)d_in[6];
    const float* Wo = (const float*)d_in[7];
    const float* bo = (const float*)d_in[8];
    float* out = (float*)d_out;
    (void)in_sizes; (void)n_in; (void)out_size;

    __half *h, *att, *wh, *wl;
    float *pq, *pk, *v, *kvp, *zp, *kv, *z;
    cudaGetSymbolAddress((void**)&h,   g_h);
    cudaGetSymbolAddress((void**)&att, g_att);
    cudaGetSymbolAddress((void**)&wh,  g_w_hi);
    cudaGetSymbolAddress((void**)&wl,  g_w_lo);
    cudaGetSymbolAddress((void**)&pq,  g_pq);
    cudaGetSymbolAddress((void**)&pk,  g_pk);
    cudaGetSymbolAddress((void**)&v,   g_v);
    cudaGetSymbolAddress((void**)&kvp, g_kvp);
    cudaGetSymbolAddress((void**)&zp,  g_zp);
    cudaGetSymbolAddress((void**)&kv,  g_kv);
    cudaGetSymbolAddress((void**)&z,   g_z);

    cudaFuncSetAttribute(gemm2p<0>, cudaFuncAttributeMaxDynamicSharedMemorySize, GSMEM);
    cudaFuncSetAttribute(gemm2p<1>, cudaFuncAttributeMaxDynamicSharedMemorySize, GSMEM);

    const size_t WN = (size_t)DD*DD;

    pe_add_h<<<(MM*(size_t)DD)/4/256, 256>>>(x, h);
    split_w<<<WN/4/256, 256>>>(Wq, wh + 0*WN, wl + 0*WN);
    split_w<<<WN/4/256, 256>>>(Wk, wh + 1*WN, wl + 1*WN);
    split_w<<<WN/4/256, 256>>>(Wv, wh + 2*WN, wl + 2*WN);
    split_w<<<WN/4/256, 256>>>(Wo, wh + 3*WN, wl + 3*WN);

    dim3 gproj(DD/128, MM/128);   // (8, 256)
    gemm2p<1><<<gproj, 256, GSMEM>>>(h, wh + 0*WN, wl + 0*WN, bq, pq);
    gemm2p<1><<<gproj, 256, GSMEM>>>(h, wh + 1*WN, wl + 1*WN, bk, pk);
    gemm2p<0><<<gproj, 256, GSMEM>>>(h, wh + 2*WN, wl + 2*WN, bv, v);

    kvz_part<<<dim3(BB*HH, 4), 256>>>(pk, v, kvp, zp);
    {
        const size_t KVN = (size_t)BB*HH*DHH*DHH;
        kvz_reduce<<<(unsigned)((KVN/4 + 255)/256), 256>>>(kvp, zp, kv, z);
    }
    attn_kernel<<<dim3(SS/128, BB*HH), 256>>>(pq, kv, z, att);

    gemm2p<0><<<gproj, 256, GSMEM>>>(att, wh + 3*WN, wl + 3*WN, bo, out);
}

// round 7
// speedup vs baseline: 3.8268x; 1.2870x over previous
#include <cuda_runtime.h>
#include <cuda_fp16.h>
#include <cstdint>
#include <math.h>

#define SS  2048
#define BB  16
#define DD  1024
#define HH  8
#define DHH 128
#define MM  (SS*BB)        // 32768 token rows
#define BDD (BB*DD)        // 16384
#define WSCALE 64.0f
#define INV_WSCALE (1.0f/64.0f)

// ---------------- scratch (device globals; allocation-free) ----------------
__device__ __half g_h   [(size_t)MM*DD];
__device__ __half g_att [(size_t)MM*DD];
__device__ __half g_w_hi[4][(size_t)DD*DD];
__device__ __half g_w_lo[4][(size_t)DD*DD];
__device__ float g_pq [(size_t)MM*DD];
__device__ float g_pk [(size_t)MM*DD];
__device__ float g_v  [(size_t)MM*DD];
__device__ float g_kvp[4][BB*HH*DHH*DHH];   // split-K partials
__device__ float g_zp [4][BB*HH*DHH];
__device__ float g_kv [BB*HH*DHH*DHH];
__device__ float g_z  [BB*HH*DHH];

// ---------------- helpers ----------------
__device__ __forceinline__ uint32_t smem_u32(const void* p) {
    uint32_t a;
    asm("{ .reg .u64 t; cvta.to.shared.u64 t, %1; cvt.u32.u64 %0, t; }" : "=r"(a) : "l"(p));
    return a;
}
__device__ __forceinline__ void ldsm4(uint32_t* r, uint32_t a) {
    asm volatile("ldmatrix.sync.aligned.m8n8.x4.shared.b16 {%0,%1,%2,%3}, [%4];"
        : "=r"(r[0]), "=r"(r[1]), "=r"(r[2]), "=r"(r[3]) : "r"(a));
}
__device__ __forceinline__ void ldsm2(uint32_t* r, uint32_t a) {
    asm volatile("ldmatrix.sync.aligned.m8n8.x2.shared.b16 {%0,%1}, [%2];"
        : "=r"(r[0]), "=r"(r[1]) : "r"(a));
}
__device__ __forceinline__ void mma16816h(float* c, const uint32_t* a, const uint32_t* b) {
    asm volatile("mma.sync.aligned.m16n8k16.row.col.f32.f16.f16.f32 "
        "{%0,%1,%2,%3}, {%4,%5,%6,%7}, {%8,%9}, {%0,%1,%2,%3};"
        : "+f"(c[0]), "+f"(c[1]), "+f"(c[2]), "+f"(c[3])
        : "r"(a[0]), "r"(a[1]), "r"(a[2]), "r"(a[3]), "r"(b[0]), "r"(b[1]));
}

// ---------------------------------------------------------------------------
// h = x + PE  -> fp16
// ---------------------------------------------------------------------------
__global__ void pe_add_h(const float* __restrict__ x, __half* __restrict__ h) {
    size_t i4 = (size_t)blockIdx.x * blockDim.x + threadIdx.x;
    size_t e  = i4 * 4;
    int d = (int)(e % DD);
    int m = (int)(e / DD);
    int s = m / BB;
    const float cc = -9.210340371976184f / (float)DD;
    float a0 = (float)s * expf((float)d * cc);
    float a1 = (float)s * expf((float)(d + 2) * cc);
    float4 xv = reinterpret_cast<const float4*>(x)[i4];
    __half2* hp = reinterpret_cast<__half2*>(h) + i4*2;
    hp[0] = __floats2half2_rn(xv.x + sinf(a0), xv.y + cosf(a0));
    hp[1] = __floats2half2_rn(xv.z + sinf(a1), xv.w + cosf(a1));
}

// scaled fp16x2 split of weights: s = W*64; hi = fp16(s); lo = fp16(s - hi)
__global__ void split_w(const float* __restrict__ src,
                        __half* __restrict__ hi, __half* __restrict__ lo) {
    size_t i4 = (size_t)blockIdx.x * blockDim.x + threadIdx.x;
    float4 v = reinterpret_cast<const float4*>(src)[i4];
    float s0 = v.x*WSCALE, s1 = v.y*WSCALE, s2 = v.z*WSCALE, s3 = v.w*WSCALE;
    __half h0 = __float2half_rn(s0), h1 = __float2half_rn(s1);
    __half h2 = __float2half_rn(s2), h3 = __float2half_rn(s3);
    __half l0 = __float2half_rn(s0 - __half2float(h0));
    __half l1 = __float2half_rn(s1 - __half2float(h1));
    __half l2 = __float2half_rn(s2 - __half2float(h2));
    __half l3 = __float2half_rn(s3 - __half2float(h3));
    __half2* hp = reinterpret_cast<__half2*>(hi) + i4*2;
    __half2* lp = reinterpret_cast<__half2*>(lo) + i4*2;
    hp[0] = __halves2half2(h0,h1); hp[1] = __halves2half2(h2,h3);
    lp[0] = __halves2half2(l0,l1); lp[1] = __halves2half2(l2,l3);
}

// ---------------------------------------------------------------------------
// fp16 GEMM, NPASS in {1,2}: C[m,n] = act( (sum_k A[m,k]*(Wh[+Wl])[n,k])/64 + b[n] )
// CTA 128x128, 256 thr (2x4 warps, warp tile 64x32), K-chunk 32, dbl-buffered.
// ---------------------------------------------------------------------------
#define KC2   32
#define NKC   (DD/KC2)        // 32
#define TPADB 80              // bytes per padded row (64B data + 16B pad)
#define TBYTES (128*TPADB)    // 10240

template<int ACT, int NPASS>
__global__ void __launch_bounds__(256) gemm2p(
    const __half* __restrict__ Ag,
    const __half* __restrict__ Bhg, const __half* __restrict__ Blg,
    const float* __restrict__ bias, float* __restrict__ C) {
    constexpr int NT  = 1 + NPASS;       // tiles per stage
    constexpr int STG = NT * TBYTES;
    extern __shared__ char sm[];
    const int tid = threadIdx.x;
    const int l   = tid & 31;
    const int wid = tid >> 5;
    const int wm  = wid >> 2;       // 0..1
    const int wn  = wid & 3;        // 0..3
    const int m0  = blockIdx.y * 128;
    const int n0  = blockIdx.x * 128;

    const __half* srcs[3] = {Ag, Bhg, Blg};
    const int r0s[3] = {m0, n0, n0};
    const int lrow0 = tid >> 2;      // 0..63
    const int lcol  = tid & 3;       // 0..3 (16B chunk)

    // preload chunk 0 into stage 0
#pragma unroll
    for (int t = 0; t < NT; t++) {
        const float4* gp = reinterpret_cast<const float4*>(srcs[t]);
        char* tp = sm + t*TBYTES;
#pragma unroll
        for (int i = 0; i < 2; i++) {
            int r = lrow0 + i*64;
            float4 v = gp[((size_t)(r0s[t] + r) * DD) / 8 + lcol];
            *reinterpret_cast<float4*>(tp + r*TPADB + lcol*16) = v;
        }
    }
    __syncthreads();

    float acc[4][4][4];
#pragma unroll
    for (int mt = 0; mt < 4; mt++)
#pragma unroll
        for (int nt = 0; nt < 4; nt++)
#pragma unroll
            for (int i = 0; i < 4; i++) acc[mt][nt][i] = 0.f;

    const uint32_t sbase = smem_u32(sm);
    const uint32_t aoff0 = (uint32_t)((wm*64 + (l & 15)) * TPADB + ((l >> 4) << 4));
    const uint32_t boff0 = (uint32_t)((wn*32 + (l & 7)) * TPADB + (((l >> 3) & 1) << 4));

    for (int c = 0; c < NKC; c++) {
        const uint32_t cb = sbase + (c & 1)*STG;
        float4 pre[6];
        if (c < NKC - 1) {
            const int kc = (c + 1) * KC2;
#pragma unroll
            for (int t = 0; t < NT; t++) {
                const float4* gp = reinterpret_cast<const float4*>(srcs[t]);
#pragma unroll
                for (int i = 0; i < 2; i++) {
                    int r = lrow0 + i*64;
                    pre[t*2+i] = gp[((size_t)(r0s[t] + r) * DD + kc) / 8 + lcol];
                }
            }
        }

#pragma unroll
        for (int ks = 0; ks < 2; ks++) {
            const uint32_t a_b  = cb + aoff0 + ks*32;
            const uint32_t bh_b = cb + 1*TBYTES + boff0 + ks*32;

            uint32_t ah[4][4], bh[4][2];
#pragma unroll
            for (int mt = 0; mt < 4; mt++) ldsm4(ah[mt], a_b + mt*16*TPADB);
#pragma unroll
            for (int nt = 0; nt < 4; nt++) ldsm2(bh[nt], bh_b + nt*8*TPADB);
#pragma unroll
            for (int mt = 0; mt < 4; mt++)
#pragma unroll
                for (int nt = 0; nt < 4; nt++)
                    mma16816h(acc[mt][nt], ah[mt], bh[nt]);
            if (NPASS == 2) {
                const uint32_t bl_b = cb + 2*TBYTES + boff0 + ks*32;
                uint32_t bx[4][2];
#pragma unroll
                for (int nt = 0; nt < 4; nt++) ldsm2(bx[nt], bl_b + nt*8*TPADB);
#pragma unroll
                for (int mt = 0; mt < 4; mt++)
#pragma unroll
                    for (int nt = 0; nt < 4; nt++)
                        mma16816h(acc[mt][nt], ah[mt], bx[nt]);
            }
        }

        if (c < NKC - 1) {
            char* nb = sm + ((c + 1) & 1)*STG;
#pragma unroll
            for (int t = 0; t < NT; t++) {
#pragma unroll
                for (int i = 0; i < 2; i++) {
                    int r = lrow0 + i*64;
                    *reinterpret_cast<float4*>(nb + t*TBYTES + r*TPADB + lcol*16) = pre[t*2+i];
                }
            }
        }
        __syncthreads();
    }

    // epilogue
    const int gi = l >> 2, ti = l & 3;
#pragma unroll
    for (int mt = 0; mt < 4; mt++) {
        const int ra = m0 + wm*64 + mt*16 + gi;
        const int rb = ra + 8;
#pragma unroll
        for (int nt = 0; nt < 4; nt++) {
            const int col = n0 + wn*32 + nt*8 + ti*2;
            const float b0 = bias[col], b1 = bias[col + 1];
            float u0 = acc[mt][nt][0]*INV_WSCALE + b0;
            float u1 = acc[mt][nt][1]*INV_WSCALE + b1;
            float u2 = acc[mt][nt][2]*INV_WSCALE + b0;
            float u3 = acc[mt][nt][3]*INV_WSCALE + b1;
            if (ACT) {
                u0 = (u0 > 0.f) ? (u0 + 1.f) : expf(u0);
                u1 = (u1 > 0.f) ? (u1 + 1.f) : expf(u1);
                u2 = (u2 > 0.f) ? (u2 + 1.f) : expf(u2);
                u3 = (u3 > 0.f) ? (u3 + 1.f) : expf(u3);
            }
            float2 o01; o01.x = u0; o01.y = u1;
            float2 o23; o23.x = u2; o23.y = u3;
            *reinterpret_cast<float2*>(C + (size_t)ra*DD + col) = o01;
            *reinterpret_cast<float2*>(C + (size_t)rb*DD + col) = o23;
        }
    }
}

// ---------------------------------------------------------------------------
// kvz split-K: per (pair, chunk): partial kv/z over 512 s values (fp32)
// ---------------------------------------------------------------------------
__global__ void __launch_bounds__(256) kvz_part(const float* __restrict__ pk,
                                                const float* __restrict__ v,
                                                float* __restrict__ kvp,
                                                float* __restrict__ zp) {
    __shared__ float Ps[2][8][128];
    __shared__ float Vs[2][8][128];
    const int pair  = blockIdx.x;
    const int chunk = blockIdx.y;
    const size_t base = (size_t)(pair / HH) * DD + (size_t)(pair % HH) * DHH
                      + (size_t)chunk * 512 * BDD;
    const int tid = threadIdx.x;
    const int tx  = tid & 15, ty = tid >> 4;
    const int si  = tid >> 5;
    const int c4  = (tid & 31) << 2;
    const float* Pp = pk + (size_t)si * BDD + base + c4;
    const float* Vp = v  + (size_t)si * BDD + base + c4;

    float acc[8][8]; float zacc[8];
#pragma unroll
    for (int i = 0; i < 8; i++) {
        zacc[i] = 0.f;
#pragma unroll
        for (int j = 0; j < 8; j++) acc[i][j] = 0.f;
    }

    *reinterpret_cast<float4*>(&Ps[0][si][c4]) = *reinterpret_cast<const float4*>(Pp);
    *reinterpret_cast<float4*>(&Vs[0][si][c4]) = *reinterpret_cast<const float4*>(Vp);
    __syncthreads();

    int buf = 0;
    for (int sc = 0; sc < 512/8; sc++) {
        float4 pv2, vv2;
        if (sc < 512/8 - 1) {
            pv2 = *reinterpret_cast<const float4*>(Pp + (size_t)(sc+1)*8*BDD);
            vv2 = *reinterpret_cast<const float4*>(Vp + (size_t)(sc+1)*8*BDD);
        }
#pragma unroll
        for (int kk = 0; kk < 8; kk++) {
            float a[8], b[8];
            *reinterpret_cast<float4*>(a)   = *reinterpret_cast<const float4*>(&Ps[buf][kk][ty*8]);
            *reinterpret_cast<float4*>(a+4) = *reinterpret_cast<const float4*>(&Ps[buf][kk][ty*8+4]);
            *reinterpret_cast<float4*>(b)   = *reinterpret_cast<const float4*>(&Vs[buf][kk][tx*8]);
            *reinterpret_cast<float4*>(b+4) = *reinterpret_cast<const float4*>(&Vs[buf][kk][tx*8+4]);
#pragma unroll
            for (int i = 0; i < 8; i++) {
                zacc[i] += a[i];
#pragma unroll
                for (int j = 0; j < 8; j++)
                    acc[i][j] += a[i] * b[j];
            }
        }
        if (sc < 512/8 - 1) {
            buf ^= 1;
            *reinterpret_cast<float4*>(&Ps[buf][si][c4]) = pv2;
            *reinterpret_cast<float4*>(&Vs[buf][si][c4]) = vv2;
            __syncthreads();
        }
    }

    float* kvb = kvp + (size_t)chunk * (BB*HH*DHH*DHH) + (size_t)pair * DHH * DHH;
#pragma unroll
    for (int i = 0; i < 8; i++) {
        float* op = kvb + (size_t)(ty*8 + i) * DHH + tx*8;
        *reinterpret_cast<float4*>(op)     = *reinterpret_cast<const float4*>(&acc[i][0]);
        *reinterpret_cast<float4*>(op + 4) = *reinterpret_cast<const float4*>(&acc[i][4]);
    }
    if (tx == 0) {
#pragma unroll
        for (int i = 0; i < 8; i++)
            zp[(size_t)chunk * (BB*HH*DHH) + pair*DHH + ty*8 + i] = zacc[i];
    }
}

__global__ void kvz_reduce(const float* __restrict__ kvp, const float* __restrict__ zp,
                           float* __restrict__ kv, float* __restrict__ z) {
    const size_t KVN = (size_t)BB*HH*DHH*DHH;
    size_t i4 = (size_t)blockIdx.x * blockDim.x + threadIdx.x;
    if (i4 < KVN/4) {
        float4 s = reinterpret_cast<const float4*>(kvp)[i4];
#pragma unroll
        for (int c = 1; c < 4; c++) {
            float4 t = reinterpret_cast<const float4*>(kvp + c*KVN)[i4];
            s.x += t.x; s.y += t.y; s.z += t.z; s.w += t.w;
        }
        reinterpret_cast<float4*>(kv)[i4] = s;
    }
    const size_t ZN = BB*HH*DHH;
    if (i4 < ZN) {
        float s = zp[i4] + zp[ZN + i4] + zp[2*ZN + i4] + zp[3*ZN + i4];
        z[i4] = s;
    }
}

// ---------------------------------------------------------------------------
// attn: num/den + normalize (fp32), writes att as fp16
// ---------------------------------------------------------------------------
__global__ void __launch_bounds__(256) attn_kernel(const float* __restrict__ pq,
                                                   const float* __restrict__ kv,
                                                   const float* __restrict__ z,
                                                   __half* __restrict__ att) {
    __shared__ float Qs[2][8][132];
    __shared__ float Ks[2][8][128];
    __shared__ float zs[2][8];
    const int s0   = blockIdx.x * 128;
    const int pair = blockIdx.y;
    const size_t base = (size_t)(pair / HH) * DD + (size_t)(pair % HH) * DHH;
    const int tid = threadIdx.x;
    const int tx  = tid & 15, ty = tid >> 4;
    const int lr  = tid >> 1;
    const int lc  = (tid & 1) << 2;
    const float* Qp = pq + (size_t)(s0 + lr) * BDD + base + lc;
    const float* Kp = kv + (size_t)pair * DHH * DHH;
    const int di = tid >> 5, e4 = (tid & 31) << 2;

    float acc[8][8]; float dacc[8];
#pragma unroll
    for (int i = 0; i < 8; i++) {
        dacc[i] = 0.f;
#pragma unroll
        for (int j = 0; j < 8; j++) acc[i][j] = 0.f;
    }

    float4 qv = *reinterpret_cast<const float4*>(Qp);
    Qs[0][lc+0][lr]=qv.x; Qs[0][lc+1][lr]=qv.y; Qs[0][lc+2][lr]=qv.z; Qs[0][lc+3][lr]=qv.w;
    *reinterpret_cast<float4*>(&Ks[0][di][e4]) =
        *reinterpret_cast<const float4*>(Kp + (size_t)di * DHH + e4);
    if (tid < 8) zs[0][tid] = z[pair*DHH + tid];
    __syncthreads();

    int buf = 0;
    for (int kc = 0; kc < DHH/8; kc++) {
        float4 qv2, kv2; float zreg = 0.f;
        if (kc < DHH/8 - 1) {
            qv2 = *reinterpret_cast<const float4*>(Qp + (kc+1)*8);
            kv2 = *reinterpret_cast<const float4*>(Kp + (size_t)((kc+1)*8 + di) * DHH + e4);
            if (tid < 8) zreg = z[pair*DHH + (kc+1)*8 + tid];
        }
#pragma unroll
        for (int kk = 0; kk < 8; kk++) {
            float a[8], b[8];
            *reinterpret_cast<float4*>(a)   = *reinterpret_cast<const float4*>(&Qs[buf][kk][ty*8]);
            *reinterpret_cast<float4*>(a+4) = *reinterpret_cast<const float4*>(&Qs[buf][kk][ty*8+4]);
            *reinterpret_cast<float4*>(b)   = *reinterpret_cast<const float4*>(&Ks[buf][kk][tx*8]);
            *reinterpret_cast<float4*>(b+4) = *reinterpret_cast<const float4*>(&Ks[buf][kk][tx*8+4]);
            float zv = zs[buf][kk];
#pragma unroll
            for (int i = 0; i < 8; i++) {
                dacc[i] += a[i] * zv;
#pragma unroll
                for (int j = 0; j < 8; j++)
                    acc[i][j] += a[i] * b[j];
            }
        }
        if (kc < DHH/8 - 1) {
            buf ^= 1;
            Qs[buf][lc+0][lr]=qv2.x; Qs[buf][lc+1][lr]=qv2.y; Qs[buf][lc+2][lr]=qv2.z; Qs[buf][lc+3][lr]=qv2.w;
            *reinterpret_cast<float4*>(&Ks[buf][di][e4]) = kv2;
            if (tid < 8) zs[buf][tid] = zreg;
            __syncthreads();
        }
    }

#pragma unroll
    for (int i = 0; i < 8; i++) {
        float inv = 1.f / (dacc[i] + 1e-6f);
        __half2 ho[4];
#pragma unroll
        for (int j = 0; j < 4; j++)
            ho[j] = __floats2half2_rn(acc[i][2*j] * inv, acc[i][2*j+1] * inv);
        size_t off = (size_t)(s0 + ty*8 + i) * BDD + base + tx*8;
        *reinterpret_cast<uint4*>(att + off) = *reinterpret_cast<uint4*>(ho);
    }
}

// ---------------------------------------------------------------------------
extern "C" void kernel_launch(void* const* d_in, const int* in_sizes, int n_in,
                              void* d_out, int out_size) {
    const float* x  = (const float*)d_in[0];
    const float* Wq = (const float*)d_in[1];
    const float* bq = (const float*)d_in[2];
    const float* Wk = (const float*)d_in[3];
    const float* bk = (const float*)d_in[4];
    const float* Wv = (const float*)d_in[5];
    const float* bv = (const float*)d_in[6];
    const float* Wo = (const float*)d_in[7];
    const float* bo = (const float*)d_in[8];
    float* out = (float*)d_out;
    (void)in_sizes; (void)n_in; (void)out_size;

    __half *h, *att, *wh, *wl;
    float *pq, *pk, *v, *kvp, *zp, *kv, *z;
    cudaGetSymbolAddress((void**)&h,   g_h);
    cudaGetSymbolAddress((void**)&att, g_att);
    cudaGetSymbolAddress((void**)&wh,  g_w_hi);
    cudaGetSymbolAddress((void**)&wl,  g_w_lo);
    cudaGetSymbolAddress((void**)&pq,  g_pq);
    cudaGetSymbolAddress((void**)&pk,  g_pk);
    cudaGetSymbolAddress((void**)&v,   g_v);
    cudaGetSymbolAddress((void**)&kvp, g_kvp);
    cudaGetSymbolAddress((void**)&zp,  g_zp);
    cudaGetSymbolAddress((void**)&kv,  g_kv);
    cudaGetSymbolAddress((void**)&z,   g_z);

    const int GS2 = 2*3*TBYTES;   // 61440 (2-pass: A, Bh, Bl)
    const int GS1 = 2*2*TBYTES;   // 40960 (1-pass: A, Bh)
    cudaFuncSetAttribute((const void*)gemm2p<1,2>, cudaFuncAttributeMaxDynamicSharedMemorySize, GS2);
    cudaFuncSetAttribute((const void*)gemm2p<0,1>, cudaFuncAttributeMaxDynamicSharedMemorySize, GS1);

    const size_t WN = (size_t)DD*DD;
    dim3 gproj(DD/128, MM/128);   // (8, 256)

    // launches 1-4 (so the 2-pass GEMM is launch #5 for ncu -s 5 -c 1)
    split_w<<<WN/4/256, 256>>>(Wq, wh + 0*WN, wl + 0*WN);
    split_w<<<WN/4/256, 256>>>(Wk, wh + 1*WN, wl + 1*WN);
    split_w<<<WN/4/256, 256>>>(Wv, wh + 2*WN, wl + 2*WN);
    pe_add_h<<<(MM*(size_t)DD)/4/256, 256>>>(x, h);

    // launch #5: profiled
    gemm2p<1,2><<<gproj, 256, GS2>>>(h, wh + 0*WN, wl + 0*WN, bq, pq);
    gemm2p<1,2><<<gproj, 256, GS2>>>(h, wh + 1*WN, wl + 1*WN, bk, pk);
    gemm2p<0,1><<<gproj, 256, GS1>>>(h, wh + 2*WN, wl + 2*WN, bv, v);   // V: 1-pass

    split_w<<<WN/4/256, 256>>>(Wo, wh + 3*WN, wl + 3*WN);

    kvz_part<<<dim3(BB*HH, 4), 256>>>(pk, v, kvp, zp);
    {
        const size_t KVN = (size_t)BB*HH*DHH*DHH;
        kvz_reduce<<<(unsigned)((KVN/4 + 255)/256), 256>>>(kvp, zp, kv, z);
    }
    attn_kernel<<<dim3(SS/128, BB*HH), 256>>>(pq, kv, z, att);

    gemm2p<0,1><<<gproj, 256, GS1>>>(att, wh + 3*WN, wl + 3*WN, bo, out);  // O: 1-pass
}

// round 8
// speedup vs baseline: 4.5112x; 1.1788x over previous
#include <cuda_runtime.h>
#include <cuda_fp16.h>
#include <cstdint>
#include <math.h>

#define SS  2048
#define BB  16
#define DD  1024
#define HH  8
#define DHH 128
#define MM  (SS*BB)        // 32768 token rows
#define BDD (BB*DD)        // 16384

// ---------------- scratch (device globals; allocation-free) ----------------
__device__ __half g_h   [(size_t)MM*DD];
__device__ __half g_att [(size_t)MM*DD];
__device__ __half g_w   [4][(size_t)DD*DD];
__device__ float g_pq [(size_t)MM*DD];
__device__ float g_pk [(size_t)MM*DD];
__device__ float g_v  [(size_t)MM*DD];
__device__ float g_kvp[4][BB*HH*DHH*DHH];   // split-K partials
__device__ float g_zp [4][BB*HH*DHH];
__device__ float g_kv [BB*HH*DHH*DHH];
__device__ float g_z  [BB*HH*DHH];

// ---------------- helpers ----------------
__device__ __forceinline__ uint32_t smem_u32(const void* p) {
    uint32_t a;
    asm("{ .reg .u64 t; cvta.to.shared.u64 t, %1; cvt.u32.u64 %0, t; }" : "=r"(a) : "l"(p));
    return a;
}
__device__ __forceinline__ void ldsm4(uint32_t* r, uint32_t a) {
    asm volatile("ldmatrix.sync.aligned.m8n8.x4.shared.b16 {%0,%1,%2,%3}, [%4];"
        : "=r"(r[0]), "=r"(r[1]), "=r"(r[2]), "=r"(r[3]) : "r"(a));
}
__device__ __forceinline__ void ldsm2(uint32_t* r, uint32_t a) {
    asm volatile("ldmatrix.sync.aligned.m8n8.x2.shared.b16 {%0,%1}, [%2];"
        : "=r"(r[0]), "=r"(r[1]) : "r"(a));
}
__device__ __forceinline__ void mma16816h(float* c, const uint32_t* a, const uint32_t* b) {
    asm volatile("mma.sync.aligned.m16n8k16.row.col.f32.f16.f16.f32 "
        "{%0,%1,%2,%3}, {%4,%5,%6,%7}, {%8,%9}, {%0,%1,%2,%3};"
        : "+f"(c[0]), "+f"(c[1]), "+f"(c[2]), "+f"(c[3])
        : "r"(a[0]), "r"(a[1]), "r"(a[2]), "r"(a[3]), "r"(b[0]), "r"(b[1]));
}

// ---------------------------------------------------------------------------
// h = x + PE  -> fp16
// ---------------------------------------------------------------------------
__global__ void pe_add_h(const float* __restrict__ x, __half* __restrict__ h) {
    size_t i4 = (size_t)blockIdx.x * blockDim.x + threadIdx.x;
    size_t e  = i4 * 4;
    int d = (int)(e % DD);
    int m = (int)(e / DD);
    int s = m / BB;
    const float cc = -9.210340371976184f / (float)DD;
    float a0 = (float)s * expf((float)d * cc);
    float a1 = (float)s * expf((float)(d + 2) * cc);
    float4 xv = reinterpret_cast<const float4*>(x)[i4];
    __half2* hp = reinterpret_cast<__half2*>(h) + i4*2;
    hp[0] = __floats2half2_rn(xv.x + sinf(a0), xv.y + cosf(a0));
    hp[1] = __floats2half2_rn(xv.z + sinf(a1), xv.w + cosf(a1));
}

// fp32 -> fp16 weight conversion
__global__ void conv_w(const float* __restrict__ src, __half* __restrict__ dst) {
    size_t i4 = (size_t)blockIdx.x * blockDim.x + threadIdx.x;
    float4 v = reinterpret_cast<const float4*>(src)[i4];
    __half2* dp = reinterpret_cast<__half2*>(dst) + i4*2;
    dp[0] = __floats2half2_rn(v.x, v.y);
    dp[1] = __floats2half2_rn(v.z, v.w);
}

// ---------------------------------------------------------------------------
// 1-pass fp16 GEMM: C[m,n] = act( sum_k A[m,k]*W[n,k] + b[n] )
// CTA 128x128, 256 thr (2x4 warps, warp tile 64x32), K-chunk 32, dbl-buffered.
// smem: 2 tiles (A,B) x 2 stages = 40 KB -> 2 CTAs/SM.
// ---------------------------------------------------------------------------
#define KC2   32
#define NKC   (DD/KC2)        // 32
#define TPADB 80              // bytes per padded row (64B data + 16B pad)
#define TBYTES (128*TPADB)    // 10240
#define STG    (2*TBYTES)     // 20480 per stage
#define GSMEM  (2*STG)        // 40960

template<int ACT>
__global__ void __launch_bounds__(256) gemm1p(
    const __half* __restrict__ Ag, const __half* __restrict__ Bg,
    const float* __restrict__ bias, float* __restrict__ C) {
    extern __shared__ char sm[];
    const int tid = threadIdx.x;
    const int l   = tid & 31;
    const int wid = tid >> 5;
    const int wm  = wid >> 2;       // 0..1
    const int wn  = wid & 3;        // 0..3
    const int m0  = blockIdx.y * 128;
    const int n0  = blockIdx.x * 128;

    const __half* srcs[2] = {Ag, Bg};
    const int r0s[2] = {m0, n0};
    const int lrow0 = tid >> 2;      // 0..63
    const int lcol  = tid & 3;       // 0..3 (16B chunk)

    // preload chunk 0 into stage 0
#pragma unroll
    for (int t = 0; t < 2; t++) {
        const float4* gp = reinterpret_cast<const float4*>(srcs[t]);
        char* tp = sm + t*TBYTES;
#pragma unroll
        for (int i = 0; i < 2; i++) {
            int r = lrow0 + i*64;
            float4 v = gp[((size_t)(r0s[t] + r) * DD) / 8 + lcol];
            *reinterpret_cast<float4*>(tp + r*TPADB + lcol*16) = v;
        }
    }
    __syncthreads();

    float acc[4][4][4];
#pragma unroll
    for (int mt = 0; mt < 4; mt++)
#pragma unroll
        for (int nt = 0; nt < 4; nt++)
#pragma unroll
            for (int i = 0; i < 4; i++) acc[mt][nt][i] = 0.f;

    const uint32_t sbase = smem_u32(sm);
    const uint32_t aoff0 = (uint32_t)((wm*64 + (l & 15)) * TPADB + ((l >> 4) << 4));
    const uint32_t boff0 = (uint32_t)((wn*32 + (l & 7)) * TPADB + (((l >> 3) & 1) << 4));

    for (int c = 0; c < NKC; c++) {
        const uint32_t cb = sbase + (c & 1)*STG;
        float4 pre[4];
        if (c < NKC - 1) {
            const int kc = (c + 1) * KC2;
#pragma unroll
            for (int t = 0; t < 2; t++) {
                const float4* gp = reinterpret_cast<const float4*>(srcs[t]);
#pragma unroll
                for (int i = 0; i < 2; i++) {
                    int r = lrow0 + i*64;
                    pre[t*2+i] = gp[((size_t)(r0s[t] + r) * DD + kc) / 8 + lcol];
                }
            }
        }

#pragma unroll
        for (int ks = 0; ks < 2; ks++) {
            const uint32_t a_b  = cb + aoff0 + ks*32;
            const uint32_t b_b  = cb + TBYTES + boff0 + ks*32;
            uint32_t ah[4][4], bh[4][2];
#pragma unroll
            for (int mt = 0; mt < 4; mt++) ldsm4(ah[mt], a_b + mt*16*TPADB);
#pragma unroll
            for (int nt = 0; nt < 4; nt++) ldsm2(bh[nt], b_b + nt*8*TPADB);
#pragma unroll
            for (int mt = 0; mt < 4; mt++)
#pragma unroll
                for (int nt = 0; nt < 4; nt++)
                    mma16816h(acc[mt][nt], ah[mt], bh[nt]);
        }

        if (c < NKC - 1) {
            char* nb = sm + ((c + 1) & 1)*STG;
#pragma unroll
            for (int t = 0; t < 2; t++) {
#pragma unroll
                for (int i = 0; i < 2; i++) {
                    int r = lrow0 + i*64;
                    *reinterpret_cast<float4*>(nb + t*TBYTES + r*TPADB + lcol*16) = pre[t*2+i];
                }
            }
        }
        __syncthreads();
    }

    // epilogue
    const int gi = l >> 2, ti = l & 3;
#pragma unroll
    for (int mt = 0; mt < 4; mt++) {
        const int ra = m0 + wm*64 + mt*16 + gi;
        const int rb = ra + 8;
#pragma unroll
        for (int nt = 0; nt < 4; nt++) {
            const int col = n0 + wn*32 + nt*8 + ti*2;
            const float b0 = bias[col], b1 = bias[col + 1];
            float u0 = acc[mt][nt][0] + b0;
            float u1 = acc[mt][nt][1] + b1;
            float u2 = acc[mt][nt][2] + b0;
            float u3 = acc[mt][nt][3] + b1;
            if (ACT) {
                u0 = (u0 > 0.f) ? (u0 + 1.f) : expf(u0);
                u1 = (u1 > 0.f) ? (u1 + 1.f) : expf(u1);
                u2 = (u2 > 0.f) ? (u2 + 1.f) : expf(u2);
                u3 = (u3 > 0.f) ? (u3 + 1.f) : expf(u3);
            }
            float2 o01; o01.x = u0; o01.y = u1;
            float2 o23; o23.x = u2; o23.y = u3;
            *reinterpret_cast<float2*>(C + (size_t)ra*DD + col) = o01;
            *reinterpret_cast<float2*>(C + (size_t)rb*DD + col) = o23;
        }
    }
}

// ---------------------------------------------------------------------------
// kvz split-K: per (pair, chunk): partial kv/z over 512 s values (fp32)
// ---------------------------------------------------------------------------
__global__ void __launch_bounds__(256) kvz_part(const float* __restrict__ pk,
                                                const float* __restrict__ v,
                                                float* __restrict__ kvp,
                                                float* __restrict__ zp) {
    __shared__ float Ps[2][8][128];
    __shared__ float Vs[2][8][128];
    const int pair  = blockIdx.x;
    const int chunk = blockIdx.y;
    const size_t base = (size_t)(pair / HH) * DD + (size_t)(pair % HH) * DHH
                      + (size_t)chunk * 512 * BDD;
    const int tid = threadIdx.x;
    const int tx  = tid & 15, ty = tid >> 4;
    const int si  = tid >> 5;
    const int c4  = (tid & 31) << 2;
    const float* Pp = pk + (size_t)si * BDD + base + c4;
    const float* Vp = v  + (size_t)si * BDD + base + c4;

    float acc[8][8]; float zacc[8];
#pragma unroll
    for (int i = 0; i < 8; i++) {
        zacc[i] = 0.f;
#pragma unroll
        for (int j = 0; j < 8; j++) acc[i][j] = 0.f;
    }

    *reinterpret_cast<float4*>(&Ps[0][si][c4]) = *reinterpret_cast<const float4*>(Pp);
    *reinterpret_cast<float4*>(&Vs[0][si][c4]) = *reinterpret_cast<const float4*>(Vp);
    __syncthreads();

    int buf = 0;
    for (int sc = 0; sc < 512/8; sc++) {
        float4 pv2, vv2;
        if (sc < 512/8 - 1) {
            pv2 = *reinterpret_cast<const float4*>(Pp + (size_t)(sc+1)*8*BDD);
            vv2 = *reinterpret_cast<const float4*>(Vp + (size_t)(sc+1)*8*BDD);
        }
#pragma unroll
        for (int kk = 0; kk < 8; kk++) {
            float a[8], b[8];
            *reinterpret_cast<float4*>(a)   = *reinterpret_cast<const float4*>(&Ps[buf][kk][ty*8]);
            *reinterpret_cast<float4*>(a+4) = *reinterpret_cast<const float4*>(&Ps[buf][kk][ty*8+4]);
            *reinterpret_cast<float4*>(b)   = *reinterpret_cast<const float4*>(&Vs[buf][kk][tx*8]);
            *reinterpret_cast<float4*>(b+4) = *reinterpret_cast<const float4*>(&Vs[buf][kk][tx*8+4]);
#pragma unroll
            for (int i = 0; i < 8; i++) {
                zacc[i] += a[i];
#pragma unroll
                for (int j = 0; j < 8; j++)
                    acc[i][j] += a[i] * b[j];
            }
        }
        if (sc < 512/8 - 1) {
            buf ^= 1;
            *reinterpret_cast<float4*>(&Ps[buf][si][c4]) = pv2;
            *reinterpret_cast<float4*>(&Vs[buf][si][c4]) = vv2;
            __syncthreads();
        }
    }

    float* kvb = kvp + (size_t)chunk * (BB*HH*DHH*DHH) + (size_t)pair * DHH * DHH;
#pragma unroll
    for (int i = 0; i < 8; i++) {
        float* op = kvb + (size_t)(ty*8 + i) * DHH + tx*8;
        *reinterpret_cast<float4*>(op)     = *reinterpret_cast<const float4*>(&acc[i][0]);
        *reinterpret_cast<float4*>(op + 4) = *reinterpret_cast<const float4*>(&acc[i][4]);
    }
    if (tx == 0) {
#pragma unroll
        for (int i = 0; i < 8; i++)
            zp[(size_t)chunk * (BB*HH*DHH) + pair*DHH + ty*8 + i] = zacc[i];
    }
}

__global__ void kvz_reduce(const float* __restrict__ kvp, const float* __restrict__ zp,
                           float* __restrict__ kv, float* __restrict__ z) {
    const size_t KVN = (size_t)BB*HH*DHH*DHH;
    size_t i4 = (size_t)blockIdx.x * blockDim.x + threadIdx.x;
    if (i4 < KVN/4) {
        float4 s = reinterpret_cast<const float4*>(kvp)[i4];
#pragma unroll
        for (int c = 1; c < 4; c++) {
            float4 t = reinterpret_cast<const float4*>(kvp + c*KVN)[i4];
            s.x += t.x; s.y += t.y; s.z += t.z; s.w += t.w;
        }
        reinterpret_cast<float4*>(kv)[i4] = s;
    }
    const size_t ZN = BB*HH*DHH;
    if (i4 < ZN) {
        float s = zp[i4] + zp[ZN + i4] + zp[2*ZN + i4] + zp[3*ZN + i4];
        z[i4] = s;
    }
}

// ---------------------------------------------------------------------------
// attn: num/den + normalize (fp32), writes att as fp16
// ---------------------------------------------------------------------------
__global__ void __launch_bounds__(256) attn_kernel(const float* __restrict__ pq,
                                                   const float* __restrict__ kv,
                                                   const float* __restrict__ z,
                                                   __half* __restrict__ att) {
    __shared__ float Qs[2][8][132];
    __shared__ float Ks[2][8][128];
    __shared__ float zs[2][8];
    const int s0   = blockIdx.x * 128;
    const int pair = blockIdx.y;
    const size_t base = (size_t)(pair / HH) * DD + (size_t)(pair % HH) * DHH;
    const int tid = threadIdx.x;
    const int tx  = tid & 15, ty = tid >> 4;
    const int lr  = tid >> 1;
    const int lc  = (tid & 1) << 2;
    const float* Qp = pq + (size_t)(s0 + lr) * BDD + base + lc;
    const float* Kp = kv + (size_t)pair * DHH * DHH;
    const int di = tid >> 5, e4 = (tid & 31) << 2;

    float acc[8][8]; float dacc[8];
#pragma unroll
    for (int i = 0; i < 8; i++) {
        dacc[i] = 0.f;
#pragma unroll
        for (int j = 0; j < 8; j++) acc[i][j] = 0.f;
    }

    float4 qv = *reinterpret_cast<const float4*>(Qp);
    Qs[0][lc+0][lr]=qv.x; Qs[0][lc+1][lr]=qv.y; Qs[0][lc+2][lr]=qv.z; Qs[0][lc+3][lr]=qv.w;
    *reinterpret_cast<float4*>(&Ks[0][di][e4]) =
        *reinterpret_cast<const float4*>(Kp + (size_t)di * DHH + e4);
    if (tid < 8) zs[0][tid] = z[pair*DHH + tid];
    __syncthreads();

    int buf = 0;
    for (int kc = 0; kc < DHH/8; kc++) {
        float4 qv2, kv2; float zreg = 0.f;
        if (kc < DHH/8 - 1) {
            qv2 = *reinterpret_cast<const float4*>(Qp + (kc+1)*8);
            kv2 = *reinterpret_cast<const float4*>(Kp + (size_t)((kc+1)*8 + di) * DHH + e4);
            if (tid < 8) zreg = z[pair*DHH + (kc+1)*8 + tid];
        }
#pragma unroll
        for (int kk = 0; kk < 8; kk++) {
            float a[8], b[8];
            *reinterpret_cast<float4*>(a)   = *reinterpret_cast<const float4*>(&Qs[buf][kk][ty*8]);
            *reinterpret_cast<float4*>(a+4) = *reinterpret_cast<const float4*>(&Qs[buf][kk][ty*8+4]);
            *reinterpret_cast<float4*>(b)   = *reinterpret_cast<const float4*>(&Ks[buf][kk][tx*8]);
            *reinterpret_cast<float4*>(b+4) = *reinterpret_cast<const float4*>(&Ks[buf][kk][tx*8+4]);
            float zv = zs[buf][kk];
#pragma unroll
            for (int i = 0; i < 8; i++) {
                dacc[i] += a[i] * zv;
#pragma unroll
                for (int j = 0; j < 8; j++)
                    acc[i][j] += a[i] * b[j];
            }
        }
        if (kc < DHH/8 - 1) {
            buf ^= 1;
            Qs[buf][lc+0][lr]=qv2.x; Qs[buf][lc+1][lr]=qv2.y; Qs[buf][lc+2][lr]=qv2.z; Qs[buf][lc+3][lr]=qv2.w;
            *reinterpret_cast<float4*>(&Ks[buf][di][e4]) = kv2;
            if (tid < 8) zs[buf][tid] = zreg;
            __syncthreads();
        }
    }

#pragma unroll
    for (int i = 0; i < 8; i++) {
        float inv = 1.f / (dacc[i] + 1e-6f);
        __half2 ho[4];
#pragma unroll
        for (int j = 0; j < 4; j++)
            ho[j] = __floats2half2_rn(acc[i][2*j] * inv, acc[i][2*j+1] * inv);
        size_t off = (size_t)(s0 + ty*8 + i) * BDD + base + tx*8;
        *reinterpret_cast<uint4*>(att + off) = *reinterpret_cast<uint4*>(ho);
    }
}

// ---------------------------------------------------------------------------
extern "C" void kernel_launch(void* const* d_in, const int* in_sizes, int n_in,
                              void* d_out, int out_size) {
    const float* x  = (const float*)d_in[0];
    const float* Wq = (const float*)d_in[1];
    const float* bq = (const float*)d_in[2];
    const float* Wk = (const float*)d_in[3];
    const float* bk = (const float*)d_in[4];
    const float* Wv = (const float*)d_in[5];
    const float* bv = (const float*)d_in[6];
    const float* Wo = (const float*)d_in[7];
    const float* bo = (const float*)d_in[8];
    float* out = (float*)d_out;
    (void)in_sizes; (void)n_in; (void)out_size;

    __half *h, *att, *w;
    float *pq, *pk, *v, *kvp, *zp, *kv, *z;
    cudaGetSymbolAddress((void**)&h,   g_h);
    cudaGetSymbolAddress((void**)&att, g_att);
    cudaGetSymbolAddress((void**)&w,   g_w);
    cudaGetSymbolAddress((void**)&pq,  g_pq);
    cudaGetSymbolAddress((void**)&pk,  g_pk);
    cudaGetSymbolAddress((void**)&v,   g_v);
    cudaGetSymbolAddress((void**)&kvp, g_kvp);
    cudaGetSymbolAddress((void**)&zp,  g_zp);
    cudaGetSymbolAddress((void**)&kv,  g_kv);
    cudaGetSymbolAddress((void**)&z,   g_z);

    cudaFuncSetAttribute((const void*)gemm1p<0>, cudaFuncAttributeMaxDynamicSharedMemorySize, GSMEM);
    cudaFuncSetAttribute((const void*)gemm1p<1>, cudaFuncAttributeMaxDynamicSharedMemorySize, GSMEM);

    const size_t WN = (size_t)DD*DD;
    dim3 gproj(DD/128, MM/128);   // (8, 256)

    // launches 1-4 (so the Q GEMM is launch #5 for ncu -s 5 -c 1)
    conv_w<<<WN/4/256, 256>>>(Wq, w + 0*WN);
    conv_w<<<WN/4/256, 256>>>(Wk, w + 1*WN);
    conv_w<<<WN/4/256, 256>>>(Wv, w + 2*WN);
    pe_add_h<<<(MM*(size_t)DD)/4/256, 256>>>(x, h);

    // launch #5: profiled
    gemm1p<1><<<gproj, 256, GSMEM>>>(h, w + 0*WN, bq, pq);
    gemm1p<1><<<gproj, 256, GSMEM>>>(h, w + 1*WN, bk, pk);
    gemm1p<0><<<gproj, 256, GSMEM>>>(h, w + 2*WN, bv, v);

    conv_w<<<WN/4/256, 256>>>(Wo, w + 3*WN);

    kvz_part<<<dim3(BB*HH, 4), 256>>>(pk, v, kvp, zp);
    {
        const size_t KVN = (size_t)BB*HH*DHH*DHH;
        kvz_reduce<<<(unsigned)((KVN/4 + 255)/256), 256>>>(kvp, zp, kv, z);
    }
    attn_kernel<<<dim3(SS/128, BB*HH), 256>>>(pq, kv, z, att);

    gemm1p<0><<<gproj, 256, GSMEM>>>(att, w + 3*WN, bo, out);
}

// round 9
// speedup vs baseline: 4.9282x; 1.0924x over previous
#include <cuda_runtime.h>
#include <cuda_fp16.h>
#include <cstdint>
#include <math.h>

#define SS  2048
#define BB  16
#define DD  1024
#define HH  8
#define DHH 128
#define MM  (SS*BB)        // 32768 token rows
#define BDD (BB*DD)        // 16384

// ---------------- scratch (device globals; allocation-free) ----------------
__device__ __half g_h   [(size_t)MM*DD];
__device__ __half g_att [(size_t)MM*DD];
__device__ __half g_w   [4][(size_t)DD*DD];
__device__ __half g_pq  [(size_t)MM*DD];
__device__ __half g_pk  [(size_t)MM*DD];
__device__ __half g_v   [(size_t)MM*DD];
__device__ __half g_kvT [BB*HH*DHH*DHH];    // kv^T: [pair][e][d] fp16
__device__ float  g_z   [BB*HH*DHH];

// ---------------- helpers ----------------
__device__ __forceinline__ uint32_t smem_u32(const void* p) {
    uint32_t a;
    asm("{ .reg .u64 t; cvta.to.shared.u64 t, %1; cvt.u32.u64 %0, t; }" : "=r"(a) : "l"(p));
    return a;
}
__device__ __forceinline__ void ldsm4(uint32_t* r, uint32_t a) {
    asm volatile("ldmatrix.sync.aligned.m8n8.x4.shared.b16 {%0,%1,%2,%3}, [%4];"
        : "=r"(r[0]), "=r"(r[1]), "=r"(r[2]), "=r"(r[3]) : "r"(a));
}
__device__ __forceinline__ void ldsm2(uint32_t* r, uint32_t a) {
    asm volatile("ldmatrix.sync.aligned.m8n8.x2.shared.b16 {%0,%1}, [%2];"
        : "=r"(r[0]), "=r"(r[1]) : "r"(a));
}
__device__ __forceinline__ void mma16816h(float* c, const uint32_t* a, const uint32_t* b) {
    asm volatile("mma.sync.aligned.m16n8k16.row.col.f32.f16.f16.f32 "
        "{%0,%1,%2,%3}, {%4,%5,%6,%7}, {%8,%9}, {%0,%1,%2,%3};"
        : "+f"(c[0]), "+f"(c[1]), "+f"(c[2]), "+f"(c[3])
        : "r"(a[0]), "r"(a[1]), "r"(a[2]), "r"(a[3]), "r"(b[0]), "r"(b[1]));
}

// ---------------------------------------------------------------------------
// h = x + PE  -> fp16
// ---------------------------------------------------------------------------
__global__ void pe_add_h(const float* __restrict__ x, __half* __restrict__ h) {
    size_t i4 = (size_t)blockIdx.x * blockDim.x + threadIdx.x;
    size_t e  = i4 * 4;
    int d = (int)(e % DD);
    int m = (int)(e / DD);
    int s = m / BB;
    const float cc = -9.210340371976184f / (float)DD;
    float a0 = (float)s * expf((float)d * cc);
    float a1 = (float)s * expf((float)(d + 2) * cc);
    float4 xv = reinterpret_cast<const float4*>(x)[i4];
    __half2* hp = reinterpret_cast<__half2*>(h) + i4*2;
    hp[0] = __floats2half2_rn(xv.x + sinf(a0), xv.y + cosf(a0));
    hp[1] = __floats2half2_rn(xv.z + sinf(a1), xv.w + cosf(a1));
}

__global__ void conv_w(const float* __restrict__ src, __half* __restrict__ dst) {
    size_t i4 = (size_t)blockIdx.x * blockDim.x + threadIdx.x;
    float4 v = reinterpret_cast<const float4*>(src)[i4];
    __half2* dp = reinterpret_cast<__half2*>(dst) + i4*2;
    dp[0] = __floats2half2_rn(v.x, v.y);
    dp[1] = __floats2half2_rn(v.z, v.w);
}

// ---------------------------------------------------------------------------
// 1-pass fp16 GEMM, templated output type (OUTH=1 -> fp16 store)
// CTA 128x128, 256 thr (2x4 warps, warp tile 64x32), K-chunk 32, dbl-buffered.
// ---------------------------------------------------------------------------
#define KC2   32
#define NKC   (DD/KC2)        // 32
#define TPADB 80              // bytes per padded row (64B data + 16B pad)
#define TBYTES (128*TPADB)    // 10240
#define STG    (2*TBYTES)     // 20480 per stage
#define GSMEM  (2*STG)        // 40960

template<int ACT, int OUTH>
__global__ void __launch_bounds__(256) gemm1p(
    const __half* __restrict__ Ag, const __half* __restrict__ Bg,
    const float* __restrict__ bias, void* __restrict__ Cv) {
    extern __shared__ char sm[];
    const int tid = threadIdx.x;
    const int l   = tid & 31;
    const int wid = tid >> 5;
    const int wm  = wid >> 2;
    const int wn  = wid & 3;
    const int m0  = blockIdx.y * 128;
    const int n0  = blockIdx.x * 128;

    const __half* srcs[2] = {Ag, Bg};
    const int r0s[2] = {m0, n0};
    const int lrow0 = tid >> 2;
    const int lcol  = tid & 3;

#pragma unroll
    for (int t = 0; t < 2; t++) {
        const float4* gp = reinterpret_cast<const float4*>(srcs[t]);
        char* tp = sm + t*TBYTES;
#pragma unroll
        for (int i = 0; i < 2; i++) {
            int r = lrow0 + i*64;
            float4 v = gp[((size_t)(r0s[t] + r) * DD) / 8 + lcol];
            *reinterpret_cast<float4*>(tp + r*TPADB + lcol*16) = v;
        }
    }
    __syncthreads();

    float acc[4][4][4];
#pragma unroll
    for (int mt = 0; mt < 4; mt++)
#pragma unroll
        for (int nt = 0; nt < 4; nt++)
#pragma unroll
            for (int i = 0; i < 4; i++) acc[mt][nt][i] = 0.f;

    const uint32_t sbase = smem_u32(sm);
    const uint32_t aoff0 = (uint32_t)((wm*64 + (l & 15)) * TPADB + ((l >> 4) << 4));
    const uint32_t boff0 = (uint32_t)((wn*32 + (l & 7)) * TPADB + (((l >> 3) & 1) << 4));

    for (int c = 0; c < NKC; c++) {
        const uint32_t cb = sbase + (c & 1)*STG;
        float4 pre[4];
        if (c < NKC - 1) {
            const int kc = (c + 1) * KC2;
#pragma unroll
            for (int t = 0; t < 2; t++) {
                const float4* gp = reinterpret_cast<const float4*>(srcs[t]);
#pragma unroll
                for (int i = 0; i < 2; i++) {
                    int r = lrow0 + i*64;
                    pre[t*2+i] = gp[((size_t)(r0s[t] + r) * DD + kc) / 8 + lcol];
                }
            }
        }

#pragma unroll
        for (int ks = 0; ks < 2; ks++) {
            const uint32_t a_b  = cb + aoff0 + ks*32;
            const uint32_t b_b  = cb + TBYTES + boff0 + ks*32;
            uint32_t ah[4][4], bh[4][2];
#pragma unroll
            for (int mt = 0; mt < 4; mt++) ldsm4(ah[mt], a_b + mt*16*TPADB);
#pragma unroll
            for (int nt = 0; nt < 4; nt++) ldsm2(bh[nt], b_b + nt*8*TPADB);
#pragma unroll
            for (int mt = 0; mt < 4; mt++)
#pragma unroll
                for (int nt = 0; nt < 4; nt++)
                    mma16816h(acc[mt][nt], ah[mt], bh[nt]);
        }

        if (c < NKC - 1) {
            char* nb = sm + ((c + 1) & 1)*STG;
#pragma unroll
            for (int t = 0; t < 2; t++) {
#pragma unroll
                for (int i = 0; i < 2; i++) {
                    int r = lrow0 + i*64;
                    *reinterpret_cast<float4*>(nb + t*TBYTES + r*TPADB + lcol*16) = pre[t*2+i];
                }
            }
        }
        __syncthreads();
    }

    const int gi = l >> 2, ti = l & 3;
#pragma unroll
    for (int mt = 0; mt < 4; mt++) {
        const int ra = m0 + wm*64 + mt*16 + gi;
        const int rb = ra + 8;
#pragma unroll
        for (int nt = 0; nt < 4; nt++) {
            const int col = n0 + wn*32 + nt*8 + ti*2;
            const float b0 = bias[col], b1 = bias[col + 1];
            float u0 = acc[mt][nt][0] + b0;
            float u1 = acc[mt][nt][1] + b1;
            float u2 = acc[mt][nt][2] + b0;
            float u3 = acc[mt][nt][3] + b1;
            if (ACT) {
                u0 = (u0 > 0.f) ? (u0 + 1.f) : expf(u0);
                u1 = (u1 > 0.f) ? (u1 + 1.f) : expf(u1);
                u2 = (u2 > 0.f) ? (u2 + 1.f) : expf(u2);
                u3 = (u3 > 0.f) ? (u3 + 1.f) : expf(u3);
            }
            if (OUTH) {
                __half* C = (__half*)Cv;
                *reinterpret_cast<__half2*>(C + (size_t)ra*DD + col) = __floats2half2_rn(u0, u1);
                *reinterpret_cast<__half2*>(C + (size_t)rb*DD + col) = __floats2half2_rn(u2, u3);
            } else {
                float* C = (float*)Cv;
                float2 o01; o01.x = u0; o01.y = u1;
                float2 o23; o23.x = u2; o23.y = u3;
                *reinterpret_cast<float2*>(C + (size_t)ra*DD + col) = o01;
                *reinterpret_cast<float2*>(C + (size_t)rb*DD + col) = o23;
            }
        }
    }
}

// ---------------------------------------------------------------------------
// kvz via MMA: per pair, kvT[e][d] = sum_s v[s,e]*pk[s,d]; z[d] = sum_s pk[s,d]
// A = v^T tile [128 e][32 s], B = pk^T tile [128 d][32 s], staged transposed.
// 64 stages of 32 s, double-buffered. z accumulated during pk staging.
// ---------------------------------------------------------------------------
__global__ void __launch_bounds__(256) kvz_mma(const __half* __restrict__ pk,
                                               const __half* __restrict__ vv,
                                               __half* __restrict__ kvT,
                                               float* __restrict__ z) {
    extern __shared__ char sm[];          // 2 stages x 2 tiles x TBYTES
    __shared__ float zsm[DHH];
    const int pair = blockIdx.x;
    const size_t base = (size_t)(pair / HH) * DD + (size_t)(pair % HH) * DHH;
    const int tid = threadIdx.x;
    const int l   = tid & 31;
    const int wid = tid >> 5;
    const int wm  = wid >> 2;
    const int wn  = wid & 3;

    if (tid < DHH) zsm[tid] = 0.f;

    // thread's two loader slots per tile: idx = tid, tid+256 ; s = idx>>4, d0 = (idx&15)*8
    const int s1 = tid >> 4,        d01 = (tid & 15) << 3;
    const int s2 = (tid + 256) >> 4; // = s1 + 16, same d0
    float zpart[8];
#pragma unroll
    for (int i = 0; i < 8; i++) zpart[i] = 0.f;

    // stage 0 load + STS (s base 0)
    {
        uint4 va1 = *reinterpret_cast<const uint4*>(vv + (size_t)s1*BDD + base + d01);
        uint4 va2 = *reinterpret_cast<const uint4*>(vv + (size_t)s2*BDD + base + d01);
        uint4 pa1 = *reinterpret_cast<const uint4*>(pk + (size_t)s1*BDD + base + d01);
        uint4 pa2 = *reinterpret_cast<const uint4*>(pk + (size_t)s2*BDD + base + d01);
        __half h8[8];
        *reinterpret_cast<uint4*>(h8) = va1;
#pragma unroll
        for (int j = 0; j < 8; j++) { int i = (j + l) & 7;
            *reinterpret_cast<__half*>(sm + (d01+i)*TPADB + s1*2) = h8[i]; }
        *reinterpret_cast<uint4*>(h8) = va2;
#pragma unroll
        for (int j = 0; j < 8; j++) { int i = (j + l) & 7;
            *reinterpret_cast<__half*>(sm + (d01+i)*TPADB + s2*2) = h8[i]; }
        *reinterpret_cast<uint4*>(h8) = pa1;
#pragma unroll
        for (int j = 0; j < 8; j++) { int i = (j + l) & 7;
            zpart[i] += __half2float(h8[i]);
            *reinterpret_cast<__half*>(sm + TBYTES + (d01+i)*TPADB + s1*2) = h8[i]; }
        *reinterpret_cast<uint4*>(h8) = pa2;
#pragma unroll
        for (int j = 0; j < 8; j++) { int i = (j + l) & 7;
            zpart[i] += __half2float(h8[i]);
            *reinterpret_cast<__half*>(sm + TBYTES + (d01+i)*TPADB + s2*2) = h8[i]; }
    }
    __syncthreads();

    float acc[4][4][4];
#pragma unroll
    for (int mt = 0; mt < 4; mt++)
#pragma unroll
        for (int nt = 0; nt < 4; nt++)
#pragma unroll
            for (int i = 0; i < 4; i++) acc[mt][nt][i] = 0.f;

    const uint32_t sbase = smem_u32(sm);
    const uint32_t aoff0 = (uint32_t)((wm*64 + (l & 15)) * TPADB + ((l >> 4) << 4));
    const uint32_t boff0 = (uint32_t)((wn*32 + (l & 7)) * TPADB + (((l >> 3) & 1) << 4));

    for (int sc = 0; sc < SS/32; sc++) {
        const uint32_t cb = sbase + (sc & 1)*STG;
        uint4 va1, va2, pa1, pa2;
        if (sc < SS/32 - 1) {
            const size_t sb = (size_t)(sc + 1) * 32;
            va1 = *reinterpret_cast<const uint4*>(vv + (sb + s1)*BDD + base + d01);
            va2 = *reinterpret_cast<const uint4*>(vv + (sb + s2)*BDD + base + d01);
            pa1 = *reinterpret_cast<const uint4*>(pk + (sb + s1)*BDD + base + d01);
            pa2 = *reinterpret_cast<const uint4*>(pk + (sb + s2)*BDD + base + d01);
        }

#pragma unroll
        for (int ks = 0; ks < 2; ks++) {
            const uint32_t a_b = cb + aoff0 + ks*32;
            const uint32_t b_b = cb + TBYTES + boff0 + ks*32;
            uint32_t ah[4][4], bh[4][2];
#pragma unroll
            for (int mt = 0; mt < 4; mt++) ldsm4(ah[mt], a_b + mt*16*TPADB);
#pragma unroll
            for (int nt = 0; nt < 4; nt++) ldsm2(bh[nt], b_b + nt*8*TPADB);
#pragma unroll
            for (int mt = 0; mt < 4; mt++)
#pragma unroll
                for (int nt = 0; nt < 4; nt++)
                    mma16816h(acc[mt][nt], ah[mt], bh[nt]);
        }

        if (sc < SS/32 - 1) {
            char* nb = sm + ((sc + 1) & 1)*STG;
            __half h8[8];
            *reinterpret_cast<uint4*>(h8) = va1;
#pragma unroll
            for (int j = 0; j < 8; j++) { int i = (j + l) & 7;
                *reinterpret_cast<__half*>(nb + (d01+i)*TPADB + s1*2) = h8[i]; }
            *reinterpret_cast<uint4*>(h8) = va2;
#pragma unroll
            for (int j = 0; j < 8; j++) { int i = (j + l) & 7;
                *reinterpret_cast<__half*>(nb + (d01+i)*TPADB + s2*2) = h8[i]; }
            *reinterpret_cast<uint4*>(h8) = pa1;
#pragma unroll
            for (int j = 0; j < 8; j++) { int i = (j + l) & 7;
                zpart[i] += __half2float(h8[i]);
                *reinterpret_cast<__half*>(nb + TBYTES + (d01+i)*TPADB + s1*2) = h8[i]; }
            *reinterpret_cast<uint4*>(h8) = pa2;
#pragma unroll
            for (int j = 0; j < 8; j++) { int i = (j + l) & 7;
                zpart[i] += __half2float(h8[i]);
                *reinterpret_cast<__half*>(nb + TBYTES + (d01+i)*TPADB + s2*2) = h8[i]; }
        }
        __syncthreads();
    }

    // z reduce via shared atomics
#pragma unroll
    for (int i = 0; i < 8; i++) atomicAdd(&zsm[d01 + i], zpart[i]);

    // kvT epilogue (rows e, cols d)
    const int gi = l >> 2, ti = l & 3;
    __half* kvb = kvT + (size_t)pair * DHH * DHH;
#pragma unroll
    for (int mt = 0; mt < 4; mt++) {
        const int ra = wm*64 + mt*16 + gi;
        const int rb = ra + 8;
#pragma unroll
        for (int nt = 0; nt < 4; nt++) {
            const int col = wn*32 + nt*8 + ti*2;
            *reinterpret_cast<__half2*>(kvb + ra*DHH + col) =
                __floats2half2_rn(acc[mt][nt][0], acc[mt][nt][1]);
            *reinterpret_cast<__half2*>(kvb + rb*DHH + col) =
                __floats2half2_rn(acc[mt][nt][2], acc[mt][nt][3]);
        }
    }
    __syncthreads();
    if (tid < DHH) z[pair*DHH + tid] = zsm[tid];
}

// ---------------------------------------------------------------------------
// attn via MMA: per (s-tile 128, pair): num = pq_tile @ kvT^T (K=128),
// den = pq.z (fp32), att = num/(den+eps) -> fp16
// ---------------------------------------------------------------------------
#define TPA 272   // smem row stride bytes for 128-half rows (+16B pad)

__global__ void __launch_bounds__(256) attn_mma(const __half* __restrict__ pq,
                                                const __half* __restrict__ kvT,
                                                const float* __restrict__ z,
                                                __half* __restrict__ att) {
    extern __shared__ char sm[];          // pq tile [128][TPA], kvT tile [128][TPA]
    __shared__ float zsm[DHH];
    __shared__ float dens[128];
    const int s0   = blockIdx.x * 128;
    const int pair = blockIdx.y;
    const size_t base = (size_t)(pair / HH) * DD + (size_t)(pair % HH) * DHH;
    const int tid = threadIdx.x;
    const int l   = tid & 31;
    const int wid = tid >> 5;
    const int wm  = wid >> 2;
    const int wn  = wid & 3;

    // load tiles: 2048 uint4 each; idx -> row=idx>>4, c16=idx&15
#pragma unroll
    for (int k = 0; k < 8; k++) {
        int idx = tid + k*256;
        int row = idx >> 4, c16 = idx & 15;
        uint4 q = *reinterpret_cast<const uint4*>(pq + (size_t)(s0 + row)*BDD + base + c16*8);
        *reinterpret_cast<uint4*>(sm + row*TPA + c16*16) = q;
        uint4 kvv = *reinterpret_cast<const uint4*>(kvT + (size_t)pair*DHH*DHH + row*DHH + c16*8);
        *reinterpret_cast<uint4*>(sm + 128*TPA + row*TPA + c16*16) = kvv;
    }
    if (tid < DHH) zsm[tid] = z[pair*DHH + tid];
    __syncthreads();

    // den: thread (row = tid>>1, half = tid&1) sums 64 d's
    {
        const int row = tid >> 1, hf = tid & 1;
        const __half2* qr = reinterpret_cast<const __half2*>(sm + row*TPA + hf*128);
        float dsum = 0.f;
#pragma unroll
        for (int j = 0; j < 32; j++) {
            float2 qf = __half22float2(qr[j]);
            dsum += qf.x * zsm[hf*64 + 2*j] + qf.y * zsm[hf*64 + 2*j + 1];
        }
        dsum += __shfl_xor_sync(0xFFFFFFFF, dsum, 1);
        if (hf == 0) dens[row] = dsum;
    }

    float acc[4][4][4];
#pragma unroll
    for (int mt = 0; mt < 4; mt++)
#pragma unroll
        for (int nt = 0; nt < 4; nt++)
#pragma unroll
            for (int i = 0; i < 4; i++) acc[mt][nt][i] = 0.f;

    const uint32_t sbase = smem_u32(sm);
    const uint32_t aoff0 = (uint32_t)((wm*64 + (l & 15)) * TPA + ((l >> 4) << 4));
    const uint32_t boff0 = (uint32_t)(128*TPA + (wn*32 + (l & 7)) * TPA + (((l >> 3) & 1) << 4));

#pragma unroll
    for (int ks = 0; ks < 8; ks++) {
        uint32_t ah[4][4], bh[4][2];
#pragma unroll
        for (int mt = 0; mt < 4; mt++) ldsm4(ah[mt], sbase + aoff0 + ks*32 + mt*16*TPA);
#pragma unroll
        for (int nt = 0; nt < 4; nt++) ldsm2(bh[nt], sbase + boff0 + ks*32 + nt*8*TPA);
#pragma unroll
        for (int mt = 0; mt < 4; mt++)
#pragma unroll
            for (int nt = 0; nt < 4; nt++)
                mma16816h(acc[mt][nt], ah[mt], bh[nt]);
    }
    __syncthreads();   // dens visible

    const int gi = l >> 2, ti = l & 3;
#pragma unroll
    for (int mt = 0; mt < 4; mt++) {
        const int ra = wm*64 + mt*16 + gi;
        const int rb = ra + 8;
        const float ia = 1.f / (dens[ra] + 1e-6f);
        const float ib = 1.f / (dens[rb] + 1e-6f);
#pragma unroll
        for (int nt = 0; nt < 4; nt++) {
            const int col = wn*32 + nt*8 + ti*2;
            *reinterpret_cast<__half2*>(att + (size_t)(s0 + ra)*BDD + base + col) =
                __floats2half2_rn(acc[mt][nt][0]*ia, acc[mt][nt][1]*ia);
            *reinterpret_cast<__half2*>(att + (size_t)(s0 + rb)*BDD + base + col) =
                __floats2half2_rn(acc[mt][nt][2]*ib, acc[mt][nt][3]*ib);
        }
    }
}

// ---------------------------------------------------------------------------
extern "C" void kernel_launch(void* const* d_in, const int* in_sizes, int n_in,
                              void* d_out, int out_size) {
    const float* x  = (const float*)d_in[0];
    const float* Wq = (const float*)d_in[1];
    const float* bq = (const float*)d_in[2];
    const float* Wk = (const float*)d_in[3];
    const float* bk = (const float*)d_in[4];
    const float* Wv = (const float*)d_in[5];
    const float* bv = (const float*)d_in[6];
    const float* Wo = (const float*)d_in[7];
    const float* bo = (const float*)d_in[8];
    float* out = (float*)d_out;
    (void)in_sizes; (void)n_in; (void)out_size;

    __half *h, *att, *w, *pq, *pk, *v, *kvT;
    float *z;
    cudaGetSymbolAddress((void**)&h,   g_h);
    cudaGetSymbolAddress((void**)&att, g_att);
    cudaGetSymbolAddress((void**)&w,   g_w);
    cudaGetSymbolAddress((void**)&pq,  g_pq);
    cudaGetSymbolAddress((void**)&pk,  g_pk);
    cudaGetSymbolAddress((void**)&v,   g_v);
    cudaGetSymbolAddress((void**)&kvT, g_kvT);
    cudaGetSymbolAddress((void**)&z,   g_z);

    cudaFuncSetAttribute((const void*)gemm1p<0,0>, cudaFuncAttributeMaxDynamicSharedMemorySize, GSMEM);
    cudaFuncSetAttribute((const void*)gemm1p<0,1>, cudaFuncAttributeMaxDynamicSharedMemorySize, GSMEM);
    cudaFuncSetAttribute((const void*)gemm1p<1,1>, cudaFuncAttributeMaxDynamicSharedMemorySize, GSMEM);
    cudaFuncSetAttribute((const void*)kvz_mma, cudaFuncAttributeMaxDynamicSharedMemorySize, GSMEM);
    const int ASMEM = 2*128*TPA;   // 69632
    cudaFuncSetAttribute((const void*)attn_mma, cudaFuncAttributeMaxDynamicSharedMemorySize, ASMEM);

    const size_t WN = (size_t)DD*DD;
    dim3 gproj(DD/128, MM/128);   // (8, 256)

    conv_w<<<WN/4/256, 256>>>(Wq, w + 0*WN);
    conv_w<<<WN/4/256, 256>>>(Wk, w + 1*WN);
    conv_w<<<WN/4/256, 256>>>(Wv, w + 2*WN);
    pe_add_h<<<(MM*(size_t)DD)/4/256, 256>>>(x, h);

    gemm1p<1,1><<<gproj, 256, GSMEM>>>(h, w + 0*WN, bq, pq);
    gemm1p<1,1><<<gproj, 256, GSMEM>>>(h, w + 1*WN, bk, pk);
    gemm1p<0,1><<<gproj, 256, GSMEM>>>(h, w + 2*WN, bv, v);

    conv_w<<<WN/4/256, 256>>>(Wo, w + 3*WN);

    kvz_mma<<<BB*HH, 256, GSMEM>>>(pk, v, kvT, z);
    attn_mma<<<dim3(SS/128, BB*HH), 256, ASMEM>>>(pq, kvT, z, att);

    gemm1p<0,0><<<gproj, 256, GSMEM>>>(att, w + 3*WN, bo, out);
}